// round 1
// baseline (speedup 1.0000x reference)
#include <cuda_runtime.h>
#include <math.h>

#define TT 365
#define NN 400
#define DD 104
#define MM (TT*NN)        /* 146000 */
#define HH 4
#define HD 26
#define QKVW 312
#define CATW 208
#define EPK_CHUNK 1026
#define EPK_SPLIT 37      /* ceil(37960/1026) */

/* ------------ scratch (device globals; no allocs in kernel_launch) ------- */
__device__ float g_hcat[MM*DD];
__device__ float g_h   [MM*DD];
__device__ float g_graph[TT*NN*NN];
__device__ float g_z1  [MM*DD];
__device__ float g_qkv [MM*QKVW];
__device__ float g_kvs [NN*HH*HD*HD];
__device__ float g_ksum[NN*HH*HD];
__device__ float g_cat [MM*CATW];
__device__ float g_att0[MM*DD];
__device__ float g_att1[MM*DD];
__device__ float g_pw0 [MM*DD];
__device__ float g_pw1 [MM*DD];
__device__ float g_h1  [MM*DD];
__device__ float g_mid [MM*CATW];
__device__ float g_tmp [MM*DD];
__device__ float g_h2  [MM*DD];
__device__ float g_h2T [MM*DD];
__device__ float g_part[EPK_SPLIT*NN*DD];
__device__ float g_y   [NN*DD];
__device__ float g_ymid[NN*CATW];

/* --------------------------- generic GEMM -------------------------------- */
/* C[M,N] = act(A[M,K] @ B[K,N or N,K if transB] + bias) (+Res) , batched via
   blockIdx.z with strides; kChunk>0 => blockIdx.z selects a K-range (splitK). */
__global__ void gemm_k(const float* __restrict__ A, const float* __restrict__ B,
                       const float* __restrict__ bias, const float* __restrict__ Res,
                       float* __restrict__ C,
                       int M, int N, int K,
                       long long sA, long long sB, long long sC,
                       int transB, int act, int kChunk)
{
    const int bz = blockIdx.z;
    const float* Ab = A + (long long)bz * sA;
    const float* Bb = B + (long long)bz * sB;
    float* Cb = C + (long long)bz * sC;
    int k0 = 0, k1 = K;
    if (kChunk > 0){ k0 = bz*kChunk; k1 = min(K, k0 + kChunk); }

    __shared__ float Ast[16][68];
    __shared__ float Bs [16][68];

    const int tid = threadIdx.x;
    const int tx = tid & 15, ty = tid >> 4;
    const int rowBase = blockIdx.y * 64;
    const int colBase = blockIdx.x * 64;

    float acc[4][4];
    #pragma unroll
    for (int i=0;i<4;i++){
        #pragma unroll
        for (int j=0;j<4;j++) acc[i][j]=0.f;
    }

    for (int kk = k0; kk < k1; kk += 16){
        #pragma unroll
        for (int i=0;i<4;i++){
            int idx = tid + i*256;
            int m = idx >> 4, kq = idx & 15;
            int gm = rowBase + m, gk = kk + kq;
            float v = 0.f;
            if (gm < M && gk < k1) v = Ab[(long long)gm*K + gk];
            Ast[kq][m] = v;
        }
        #pragma unroll
        for (int i=0;i<4;i++){
            int idx = tid + i*256;
            int kq = idx >> 6, n = idx & 63;
            int gk = kk + kq, gn = colBase + n;
            float v = 0.f;
            if (gn < N && gk < k1)
                v = transB ? Bb[(long long)gn*K + gk] : Bb[(long long)gk*N + gn];
            Bs[kq][n] = v;
        }
        __syncthreads();
        #pragma unroll
        for (int kq=0;kq<16;kq++){
            float4 av = *reinterpret_cast<const float4*>(&Ast[kq][ty*4]);
            float4 bv = *reinterpret_cast<const float4*>(&Bs [kq][tx*4]);
            float am[4] = {av.x,av.y,av.z,av.w};
            float bn[4] = {bv.x,bv.y,bv.z,bv.w};
            #pragma unroll
            for (int i=0;i<4;i++){
                #pragma unroll
                for (int j=0;j<4;j++) acc[i][j] += am[i]*bn[j];
            }
        }
        __syncthreads();
    }
    #pragma unroll
    for (int i=0;i<4;i++){
        int gm = rowBase + ty*4 + i;
        if (gm >= M) continue;
        #pragma unroll
        for (int j=0;j<4;j++){
            int gn = colBase + tx*4 + j;
            if (gn >= N) continue;
            float v = acc[i][j];
            if (bias) v += bias[gn];
            if (act == 1) v = fmaxf(v, 0.f);
            if (Res) v += Res[(long long)gm*N + gn];
            Cb[(long long)gm*N + gn] = v;
        }
    }
}

/* ------------------------- elementwise / fused --------------------------- */
__global__ void build_hcat_k(const float* __restrict__ x, const float* __restrict__ W_in,
                             const float* __restrict__ b_in, const float* __restrict__ adp,
                             float* __restrict__ out)
{
    long long idx = (long long)blockIdx.x*blockDim.x + threadIdx.x;
    if (idx >= (long long)MM*DD) return;
    int d = (int)(idx % DD);
    long long tn = idx / DD;          /* t*NN + n (t-major) */
    int n = (int)(tn % NN);
    int t = (int)(tn / NN);
    float v;
    if (d < 24){
        const float* xr = x + ((long long)n*TT + t)*3;
        v = b_in[d] + xr[0]*W_in[d] + xr[1]*W_in[24+d] + xr[2]*W_in[48+d];
    } else {
        v = adp[tn*80 + (d-24)];
    }
    out[idx] = v;
}

__global__ void softmax_k(float* __restrict__ g)
{
    long long row = (long long)blockIdx.x*4 + (threadIdx.x>>5);
    if (row >= MM) return;
    int lane = threadIdx.x & 31;
    float* p = g + row*NN;
    float r[13];
    float mx = -3.4e38f;
    #pragma unroll
    for (int i=0;i<13;i++){ int j=lane+i*32; r[i] = (j<NN)? p[j] : -3.4e38f; mx = fmaxf(mx, r[i]); }
    #pragma unroll
    for (int o=16;o;o>>=1) mx = fmaxf(mx, __shfl_xor_sync(0xffffffffu, mx, o));
    float s = 0.f;
    #pragma unroll
    for (int i=0;i<13;i++){ int j=lane+i*32; if (j<NN){ r[i]=expf(r[i]-mx); s+=r[i]; } }
    #pragma unroll
    for (int o=16;o;o>>=1) s += __shfl_xor_sync(0xffffffffu, s, o);
    float inv = 1.f/s;
    #pragma unroll
    for (int i=0;i<13;i++){ int j=lane+i*32; if (j<NN) p[j] = r[i]*inv; }
}

/* kvs[b,h,m,d] = sum_l kn[l,m]*v[l,d] ; ksum[b,h,m] = sum_l kn[l,m] */
__global__ void attn_kvs_k(const float* __restrict__ qkv, float* __restrict__ kvs,
                           float* __restrict__ ksum, int L, int spatial)
{
    int b = blockIdx.x, h = blockIdx.y;
    __shared__ float sk[32][27];
    __shared__ float sv[32][27];
    __shared__ float ss[32];
    int tid = threadIdx.x;
    int mi[3], di[3]; bool ok[3];
    #pragma unroll
    for (int i=0;i<3;i++){ int p=tid+i*256; ok[i]=(p<676); mi[i]=p/26; di[i]=p-26*(p/26); }
    float acc[3] = {0.f,0.f,0.f};
    float asum = 0.f;
    for (int l0=0; l0<L; l0+=32){
        int lc = min(32, L-l0);
        for (int idx=tid; idx<lc*26; idx+=256){
            int r = idx/26, c = idx-r*26;
            int l = l0 + r;
            long long base = spatial ? ((long long)b*NN + l)*QKVW : ((long long)l*NN + b)*QKVW;
            sk[r][c] = qkv[base + DD   + h*HD + c];
            sv[r][c] = qkv[base + 2*DD + h*HD + c];
        }
        __syncthreads();
        if (tid < lc){
            float s=0.f;
            #pragma unroll
            for (int c=0;c<26;c++){ float k=sk[tid][c]; s += k*k; }
            ss[tid] = 1.f/fmaxf(sqrtf(s), 1e-12f);
        }
        __syncthreads();
        for (int idx=tid; idx<lc*26; idx+=256){
            int r = idx/26, c = idx-r*26;
            sk[r][c] *= ss[r];
        }
        __syncthreads();
        for (int l=0;l<lc;l++){
            #pragma unroll
            for (int i=0;i<3;i++)
                if (ok[i]) acc[i] += sk[l][mi[i]]*sv[l][di[i]];
        }
        if (tid < 26){
            for (int l=0;l<lc;l++) asum += sk[l][tid];
        }
        __syncthreads();
    }
    long long ob = ((long long)b*HH + h);
    #pragma unroll
    for (int i=0;i<3;i++){ int p=tid+i*256; if (p<676) kvs[ob*676 + p] = acc[i]; }
    if (tid<26) ksum[ob*26 + tid] = asum;
}

/* out = (qn@kvs + L*v) / (qn.ksum + L) ; one warp per (b,h,l) */
__global__ void attn_out_k(const float* __restrict__ qkv, const float* __restrict__ kvs,
                           const float* __restrict__ ksum, float* __restrict__ cat,
                           int L, int spatial)
{
    int b = blockIdx.x, h = blockIdx.y;
    int warp = threadIdx.x >> 5, lane = threadIdx.x & 31;
    __shared__ float skv[676];
    __shared__ float sks[26];
    long long ob = ((long long)b*HH + h);
    for (int idx=threadIdx.x; idx<676; idx+=128) skv[idx] = kvs[ob*676+idx];
    if (threadIdx.x < 26) sks[threadIdx.x] = ksum[ob*26+threadIdx.x];
    __syncthreads();
    int l = blockIdx.z*4 + warp;
    if (l >= L) return;
    long long base = spatial ? ((long long)b*NN + l)*QKVW : ((long long)l*NN + b)*QKVW;
    float q = (lane < 26) ? qkv[base + h*HD + lane] : 0.f;
    float sq = q*q;
    #pragma unroll
    for (int o=16;o;o>>=1) sq += __shfl_xor_sync(0xffffffffu, sq, o);
    float qn = q * (1.f/fmaxf(sqrtf(sq), 1e-12f));
    float dp = (lane<26) ? qn*sks[lane] : 0.f;
    #pragma unroll
    for (int o=16;o;o>>=1) dp += __shfl_xor_sync(0xffffffffu, dp, o);
    float den = dp + (float)L;
    float num = 0.f;
    #pragma unroll
    for (int m=0;m<26;m++){
        float qm = __shfl_sync(0xffffffffu, qn, m);
        if (lane < 26) num += qm * skv[m*26 + lane];
    }
    if (lane < 26){
        float v = qkv[base + 2*DD + h*HD + lane];
        float o = (num + (float)L * v)/den;
        long long cb = spatial ? ((long long)b*NN + l)*CATW + h*HD
                               : ((long long)l*NN + b)*CATW + DD + h*HD;
        cat[cb + lane] = o;
    }
}

/* h1 = LN(2*(h + a0*pw0 + 0.01*a1*pw1)) */
__global__ void combine_ln1_k(const float* __restrict__ h, const float* __restrict__ a0,
                              const float* __restrict__ pw0, const float* __restrict__ a1,
                              const float* __restrict__ pw1, const float* __restrict__ gam,
                              const float* __restrict__ bet, float* __restrict__ out)
{
    long long row = (long long)blockIdx.x*4 + (threadIdx.x>>5);
    if (row >= MM) return;
    int lane = threadIdx.x & 31;
    long long base = row*DD;
    float v[4]; float s = 0.f;
    #pragma unroll
    for (int i=0;i<4;i++){
        int j = lane + i*32;
        if (j < DD){
            float x = 2.f*(h[base+j] + a0[base+j]*pw0[base+j] + 0.01f*a1[base+j]*pw1[base+j]);
            v[i]=x; s+=x;
        } else v[i]=0.f;
    }
    #pragma unroll
    for (int o=16;o;o>>=1) s += __shfl_xor_sync(0xffffffffu, s, o);
    float mean = s * (1.f/DD);
    float vs = 0.f;
    #pragma unroll
    for (int i=0;i<4;i++){ int j=lane+i*32; if (j<DD){ float d=v[i]-mean; vs += d*d; } }
    #pragma unroll
    for (int o=16;o;o>>=1) vs += __shfl_xor_sync(0xffffffffu, vs, o);
    float inv = rsqrtf(vs*(1.f/DD) + 1e-5f);
    #pragma unroll
    for (int i=0;i<4;i++){ int j=lane+i*32; if (j<DD) out[base+j] = (v[i]-mean)*inv*gam[j] + bet[j]; }
}

__global__ void ln_k(const float* __restrict__ in, const float* __restrict__ gam,
                     const float* __restrict__ bet, float* __restrict__ out)
{
    long long row = (long long)blockIdx.x*4 + (threadIdx.x>>5);
    if (row >= MM) return;
    int lane = threadIdx.x & 31;
    const float* p = in + row*DD;
    float v[4]; float s = 0.f;
    #pragma unroll
    for (int i=0;i<4;i++){ int j=lane+i*32; v[i] = (j<DD)? p[j] : 0.f; s += v[i]; }
    #pragma unroll
    for (int o=16;o;o>>=1) s += __shfl_xor_sync(0xffffffffu, s, o);
    float mean = s * (1.f/DD);
    float vs = 0.f;
    #pragma unroll
    for (int i=0;i<4;i++){ int j=lane+i*32; if (j<DD){ float d=v[i]-mean; vs += d*d; } }
    #pragma unroll
    for (int o=16;o;o>>=1) vs += __shfl_xor_sync(0xffffffffu, vs, o);
    float inv = rsqrtf(vs*(1.f/DD) + 1e-5f);
    float* q = out + row*DD;
    #pragma unroll
    for (int i=0;i<4;i++){ int j=lane+i*32; if (j<DD) q[j] = (v[i]-mean)*inv*gam[j] + bet[j]; }
}

/* h2 [T,N,D] -> h2T [N, T*D] */
__global__ void transpose_k(const float* __restrict__ in, float* __restrict__ out)
{
    long long idx = (long long)blockIdx.x*blockDim.x + threadIdx.x;
    if (idx >= (long long)MM*DD) return;
    int d = (int)(idx % DD);
    long long tn = idx / DD;
    int n = (int)(tn % NN);
    int t = (int)(tn / NN);
    out[(long long)n*(TT*DD) + (long long)t*DD + d] = in[idx];
}

__global__ void ep_reduce_k(const float* __restrict__ part, const float* __restrict__ ep_b,
                            float* __restrict__ y)
{
    int idx = blockIdx.x*blockDim.x + threadIdx.x;
    if (idx >= NN*DD) return;
    float s = ep_b[idx % DD];
    #pragma unroll
    for (int j=0;j<EPK_SPLIT;j++) s += part[(long long)j*(NN*DD) + idx];
    y[idx] = s;
}

/* ------------------------------ host side -------------------------------- */
static void gemm(const float*A,const float*B,const float*bias,const float*Res,float*C,
                 int M,int N,int K,long long sA,long long sB,long long sC,
                 int transB,int act,int kChunk,int batch)
{
    dim3 grid((N+63)/64, (M+63)/64, batch);
    gemm_k<<<grid, 256>>>(A,B,bias,Res,C,M,N,K,sA,sB,sC,transB,act,kChunk);
}

extern "C" void kernel_launch(void* const* d_in, const int* in_sizes, int n_in,
                              void* d_out, int out_size)
{
    const float* x     = (const float*)d_in[0];
    const float* W_in  = (const float*)d_in[1];
    const float* b_in  = (const float*)d_in[2];
    const float* adp   = (const float*)d_in[3];
    const float* W_tp  = (const float*)d_in[4];
    const float* b_tp  = (const float*)d_in[5];
    const float* qkv_w = (const float*)d_in[6];
    const float* op_w  = (const float*)d_in[7];
    const float* op_b  = (const float*)d_in[8];
    const float* pw_w  = (const float*)d_in[9];
    const float* pw_b  = (const float*)d_in[10];
    const float* fc_w1 = (const float*)d_in[11];
    const float* fc_b1 = (const float*)d_in[12];
    const float* fc_w2 = (const float*)d_in[13];
    const float* fc_b2 = (const float*)d_in[14];
    const float* ln1_g = (const float*)d_in[15];
    const float* ln1_b = (const float*)d_in[16];
    const float* ln2_g = (const float*)d_in[17];
    const float* ln2_b = (const float*)d_in[18];
    const float* ep_w  = (const float*)d_in[19];
    const float* ep_b  = (const float*)d_in[20];
    const float* enc_w1= (const float*)d_in[21];
    const float* enc_b1= (const float*)d_in[22];
    const float* enc_w2= (const float*)d_in[23];
    const float* enc_b2= (const float*)d_in[24];
    const float* out_w = (const float*)d_in[25];
    const float* out_b = (const float*)d_in[26];
    float* out = (float*)d_out;

    float *hcat,*h,*graph,*z1,*qkv,*kvs,*ksum,*cat,*att0,*att1,*pw0,*pw1,*h1,*mid,*tmp,*h2,*h2T,*part,*y,*ymid;
    cudaGetSymbolAddress((void**)&hcat, g_hcat);
    cudaGetSymbolAddress((void**)&h,    g_h);
    cudaGetSymbolAddress((void**)&graph,g_graph);
    cudaGetSymbolAddress((void**)&z1,   g_z1);
    cudaGetSymbolAddress((void**)&qkv,  g_qkv);
    cudaGetSymbolAddress((void**)&kvs,  g_kvs);
    cudaGetSymbolAddress((void**)&ksum, g_ksum);
    cudaGetSymbolAddress((void**)&cat,  g_cat);
    cudaGetSymbolAddress((void**)&att0, g_att0);
    cudaGetSymbolAddress((void**)&att1, g_att1);
    cudaGetSymbolAddress((void**)&pw0,  g_pw0);
    cudaGetSymbolAddress((void**)&pw1,  g_pw1);
    cudaGetSymbolAddress((void**)&h1,   g_h1);
    cudaGetSymbolAddress((void**)&mid,  g_mid);
    cudaGetSymbolAddress((void**)&tmp,  g_tmp);
    cudaGetSymbolAddress((void**)&h2,   g_h2);
    cudaGetSymbolAddress((void**)&h2T,  g_h2T);
    cudaGetSymbolAddress((void**)&part, g_part);
    cudaGetSymbolAddress((void**)&y,    g_y);
    cudaGetSymbolAddress((void**)&ymid, g_ymid);

    const long long tot = (long long)MM*DD;

    /* 1. hcat = [x@W_in + b_in, adp]  -> [T,N,104] */
    build_hcat_k<<<(unsigned)((tot+255)/256), 256>>>(x, W_in, b_in, adp, hcat);

    /* 2. h = hcat @ W_tp + b_tp */
    gemm(hcat, W_tp, b_tp, nullptr, h, MM, DD, DD, 0,0,0, 0,0,0, 1);

    /* 3. graph = relu(adp_t @ adp_t^T), batched over t */
    gemm(adp, adp, nullptr, nullptr, graph, NN, NN, 80,
         (long long)NN*80, (long long)NN*80, (long long)NN*NN, 1, 1, 0, TT);

    /* 4. softmax rows */
    softmax_k<<<(MM+3)/4, 128>>>(graph);

    /* 5. z1 = graph @ h_t, batched over t */
    gemm(graph, h, nullptr, nullptr, z1, NN, DD, NN,
         (long long)NN*NN, (long long)NN*DD, (long long)NN*DD, 0, 0, 0, TT);

    /* 6. att0 = fast_attn(h, weights[0]) */
    gemm(h, qkv_w, nullptr, nullptr, qkv, MM, QKVW, DD, 0,0,0, 0,0,0, 1);
    attn_kvs_k<<<dim3(TT,HH), 256>>>(qkv, kvs, ksum, NN, 1);
    attn_out_k<<<dim3(TT,HH,(NN+3)/4), 128>>>(qkv, kvs, ksum, cat, NN, 1);
    attn_kvs_k<<<dim3(NN,HH), 256>>>(qkv, kvs, ksum, TT, 0);
    attn_out_k<<<dim3(NN,HH,(TT+3)/4), 128>>>(qkv, kvs, ksum, cat, TT, 0);
    gemm(cat, op_w, op_b, nullptr, att0, MM, DD, CATW, 0,0,0, 0,0,0, 1);

    /* 7. att1 = fast_attn(z1, weights[1]) */
    gemm(z1, qkv_w + DD*QKVW, nullptr, nullptr, qkv, MM, QKVW, DD, 0,0,0, 0,0,0, 1);
    attn_kvs_k<<<dim3(TT,HH), 256>>>(qkv, kvs, ksum, NN, 1);
    attn_out_k<<<dim3(TT,HH,(NN+3)/4), 128>>>(qkv, kvs, ksum, cat, NN, 1);
    attn_kvs_k<<<dim3(NN,HH), 256>>>(qkv, kvs, ksum, TT, 0);
    attn_out_k<<<dim3(NN,HH,(TT+3)/4), 128>>>(qkv, kvs, ksum, cat, TT, 0);
    gemm(cat, op_w + CATW*DD, op_b + DD, nullptr, att1, MM, DD, CATW, 0,0,0, 0,0,0, 1);

    /* 8. pw projections */
    gemm(h,    pw_w,         pw_b,      nullptr, pw0, MM, DD, DD, 0,0,0, 0,0,0, 1);
    gemm(att0, pw_w + DD*DD, pw_b + DD, nullptr, pw1, MM, DD, DD, 0,0,0, 0,0,0, 1);

    /* 9. h1 = LN(2*(h + att0*pw0 + 0.01*att1*pw1)) */
    combine_ln1_k<<<(MM+3)/4, 128>>>(h, att0, pw0, att1, pw1, ln1_g, ln1_b, h1);

    /* 10. h2 = LN(h1 + MLP(h1)) */
    gemm(h1,  fc_w1, fc_b1, nullptr, mid, MM, CATW, DD,  0,0,0, 0,1,0, 1);
    gemm(mid, fc_w2, fc_b2, h1,      tmp, MM, DD, CATW,  0,0,0, 0,0,0, 1);
    ln_k<<<(MM+3)/4, 128>>>(tmp, ln2_g, ln2_b, h2);

    /* 11. encoder_proj: y = reshape(h2) @ ep_w + ep_b  (split-K, deterministic) */
    transpose_k<<<(unsigned)((tot+255)/256), 256>>>(h2, h2T);
    gemm(h2T, ep_w, nullptr, nullptr, part, NN, DD, TT*DD,
         0, 0, (long long)NN*DD, 0, 0, EPK_CHUNK, EPK_SPLIT);
    ep_reduce_k<<<(NN*DD+255)/256, 256>>>(part, ep_b, y);

    /* 12. three residual MLP blocks */
    for (int i=0;i<3;i++){
        gemm(y,    enc_w1 + (long long)i*DD*CATW, enc_b1 + i*CATW, nullptr, ymid, NN, CATW, DD, 0,0,0, 0,1,0, 1);
        gemm(ymid, enc_w2 + (long long)i*CATW*DD, enc_b2 + i*DD,   y,       y,    NN, DD, CATW, 0,0,0, 0,0,0, 1);
    }

    /* 13. out = y @ out_w + out_b -> [N,365] == d_out layout */
    gemm(y, out_w, out_b, nullptr, out, NN, TT, DD, 0,0,0, 0,0,0, 1);
}

// round 2
// speedup vs baseline: 1.3891x; 1.3891x over previous
#include <cuda_runtime.h>
#include <math.h>
#include <stdint.h>

#define TT 365
#define NN 400
#define DD 104
#define MM (TT*NN)        /* 146000 */
#define HH 4
#define HD 26
#define QKVW 312
#define CATW 208
#define EPK_CHUNK 1040    /* divisible by 16 */
#define EPK_SPLIT 37      /* 37*1040 >= 37960 */

/* ------------ scratch (device globals; no allocs in kernel_launch) ------- */
__device__ float g_hcat[MM*DD];
__device__ float g_h   [MM*DD];
__device__ float g_graph[TT*NN*NN];
__device__ float g_z1  [MM*DD];
__device__ float g_qkv [MM*QKVW];
__device__ float g_kvs [NN*HH*HD*HD];
__device__ float g_ksum[NN*HH*HD];
__device__ float g_cat [MM*CATW];
__device__ float g_att0[MM*DD];
__device__ float g_att1[MM*DD];
__device__ float g_pw0 [MM*DD];
__device__ float g_pw1 [MM*DD];
__device__ float g_h1  [MM*DD];
__device__ float g_mid [MM*CATW];
__device__ float g_tmp [MM*DD];
__device__ float g_h2  [MM*DD];
__device__ float g_h2T [MM*DD];
__device__ float g_part[EPK_SPLIT*NN*DD];
__device__ float g_y   [NN*DD];
__device__ float g_ymid[NN*CATW];

/* ----------------------- tf32 tensor-core GEMM --------------------------- */
/* C[M,N] = act(A[M,K] @ B) + bias (+Res). transB: B is [N,K]. Batched via
   blockIdx.z (strides sA/sB/sC). kChunk>0: blockIdx.z selects K-range.
   Tile 128x64x16, 256 threads, 8 warps of 32x32, m16n8k8 tf32 mma. */
__device__ __forceinline__ uint32_t f2tf32(float v){
    uint32_t u; asm("cvt.rna.tf32.f32 %0, %1;" : "=r"(u) : "f"(v)); return u;
}

__global__ void gemm_tf32_k(const float* __restrict__ A, const float* __restrict__ B,
                            const float* __restrict__ bias, const float* __restrict__ Res,
                            float* __restrict__ C,
                            int M, int N, int K,
                            long long sA, long long sB, long long sC,
                            int transB, int act, int kChunk)
{
    const int bz = blockIdx.z;
    const float* Ab = A + (long long)bz * sA;
    const float* Bb = B + (long long)bz * sB;
    float* Cb = C + (long long)bz * sC;
    int k0 = 0, k1 = K;
    if (kChunk > 0){ k0 = bz*kChunk; k1 = min(K, k0 + kChunk); }

    __shared__ uint32_t As[16][136];   /* stride 136 -> conflict-free frag loads */
    __shared__ uint32_t Bs[16][72];

    const int tid  = threadIdx.x;
    const int lane = tid & 31;
    const int warp = tid >> 5;
    const int warpM = warp & 3;        /* 0..3 -> m offset 32*warpM */
    const int warpN = warp >> 2;       /* 0..1 -> n offset 32*warpN */
    const int grp = lane >> 2;         /* 0..7 */
    const int qid = lane & 3;          /* 0..3 */
    const int rowBase = blockIdx.y * 128;
    const int colBase = blockIdx.x * 64;

    float c[2][4][4];
    #pragma unroll
    for (int i=0;i<2;i++)
        #pragma unroll
        for (int j=0;j<4;j++)
            #pragma unroll
            for (int r=0;r<4;r++) c[i][j][r]=0.f;

    for (int kk = k0; kk < k1; kk += 16){
        /* A tile: As[k][m] = A[rowBase+m][kk+k] */
        #pragma unroll
        for (int i=0;i<8;i++){
            int idx = tid + i*256;
            int m = idx >> 4, k = idx & 15;
            int gm = rowBase + m, gk = kk + k;
            float v = (gm < M && gk < k1) ? Ab[(long long)gm*K + gk] : 0.f;
            As[k][m] = f2tf32(v);
        }
        /* B tile: Bs[k][n] */
        if (!transB){
            #pragma unroll
            for (int i=0;i<4;i++){
                int idx = tid + i*256;
                int n = idx & 63, k = idx >> 6;
                int gk = kk + k, gn = colBase + n;
                float v = (gn < N && gk < k1) ? Bb[(long long)gk*N + gn] : 0.f;
                Bs[k][n] = f2tf32(v);
            }
        } else {
            #pragma unroll
            for (int i=0;i<4;i++){
                int idx = tid + i*256;
                int k = idx & 15, n = idx >> 4;
                int gk = kk + k, gn = colBase + n;
                float v = (gn < N && gk < k1) ? Bb[(long long)gn*K + gk] : 0.f;
                Bs[k][n] = f2tf32(v);
            }
        }
        __syncthreads();

        #pragma unroll
        for (int kb=0; kb<16; kb+=8){
            uint32_t a[2][4], b[4][2];
            #pragma unroll
            for (int mt=0;mt<2;mt++){
                int r = warpM*32 + mt*16 + grp;
                a[mt][0] = As[kb+qid  ][r];
                a[mt][1] = As[kb+qid  ][r+8];
                a[mt][2] = As[kb+qid+4][r];
                a[mt][3] = As[kb+qid+4][r+8];
            }
            #pragma unroll
            for (int nt=0;nt<4;nt++){
                int cn = warpN*32 + nt*8 + grp;
                b[nt][0] = Bs[kb+qid  ][cn];
                b[nt][1] = Bs[kb+qid+4][cn];
            }
            #pragma unroll
            for (int mt=0;mt<2;mt++){
                #pragma unroll
                for (int nt=0;nt<4;nt++){
                    asm("mma.sync.aligned.m16n8k8.row.col.f32.tf32.tf32.f32 "
                        "{%0,%1,%2,%3}, {%4,%5,%6,%7}, {%8,%9}, {%0,%1,%2,%3};"
                        : "+f"(c[mt][nt][0]), "+f"(c[mt][nt][1]),
                          "+f"(c[mt][nt][2]), "+f"(c[mt][nt][3])
                        : "r"(a[mt][0]), "r"(a[mt][1]), "r"(a[mt][2]), "r"(a[mt][3]),
                          "r"(b[nt][0]), "r"(b[nt][1]));
                }
            }
        }
        __syncthreads();
    }

    /* epilogue */
    #pragma unroll
    for (int mt=0;mt<2;mt++){
        #pragma unroll
        for (int nt=0;nt<4;nt++){
            int row0 = rowBase + warpM*32 + mt*16 + grp;
            int col0 = colBase + warpN*32 + nt*8 + qid*2;
            #pragma unroll
            for (int r=0;r<4;r++){
                int row = row0 + (r>>1)*8;
                int col = col0 + (r&1);
                if (row < M && col < N){
                    float v = c[mt][nt][r];
                    if (bias) v += bias[col];
                    if (act == 1) v = fmaxf(v, 0.f);
                    if (Res) v += Res[(long long)row*N + col];
                    Cb[(long long)row*N + col] = v;
                }
            }
        }
    }
}

/* --------------------------- fp32 GEMM (small) ---------------------------- */
__global__ void gemm_k(const float* __restrict__ A, const float* __restrict__ B,
                       const float* __restrict__ bias, const float* __restrict__ Res,
                       float* __restrict__ C,
                       int M, int N, int K,
                       long long sA, long long sB, long long sC,
                       int transB, int act, int kChunk)
{
    const int bz = blockIdx.z;
    const float* Ab = A + (long long)bz * sA;
    const float* Bb = B + (long long)bz * sB;
    float* Cb = C + (long long)bz * sC;
    int k0 = 0, k1 = K;
    if (kChunk > 0){ k0 = bz*kChunk; k1 = min(K, k0 + kChunk); }

    __shared__ float Ast[16][68];
    __shared__ float Bs [16][68];

    const int tid = threadIdx.x;
    const int tx = tid & 15, ty = tid >> 4;
    const int rowBase = blockIdx.y * 64;
    const int colBase = blockIdx.x * 64;

    float acc[4][4];
    #pragma unroll
    for (int i=0;i<4;i++){
        #pragma unroll
        for (int j=0;j<4;j++) acc[i][j]=0.f;
    }

    for (int kk = k0; kk < k1; kk += 16){
        #pragma unroll
        for (int i=0;i<4;i++){
            int idx = tid + i*256;
            int m = idx >> 4, kq = idx & 15;
            int gm = rowBase + m, gk = kk + kq;
            float v = 0.f;
            if (gm < M && gk < k1) v = Ab[(long long)gm*K + gk];
            Ast[kq][m] = v;
        }
        #pragma unroll
        for (int i=0;i<4;i++){
            int idx = tid + i*256;
            int kq = idx >> 6, n = idx & 63;
            int gk = kk + kq, gn = colBase + n;
            float v = 0.f;
            if (gn < N && gk < k1)
                v = transB ? Bb[(long long)gn*K + gk] : Bb[(long long)gk*N + gn];
            Bs[kq][n] = v;
        }
        __syncthreads();
        #pragma unroll
        for (int kq=0;kq<16;kq++){
            float4 av = *reinterpret_cast<const float4*>(&Ast[kq][ty*4]);
            float4 bv = *reinterpret_cast<const float4*>(&Bs [kq][tx*4]);
            float am[4] = {av.x,av.y,av.z,av.w};
            float bn[4] = {bv.x,bv.y,bv.z,bv.w};
            #pragma unroll
            for (int i=0;i<4;i++){
                #pragma unroll
                for (int j=0;j<4;j++) acc[i][j] += am[i]*bn[j];
            }
        }
        __syncthreads();
    }
    #pragma unroll
    for (int i=0;i<4;i++){
        int gm = rowBase + ty*4 + i;
        if (gm >= M) continue;
        #pragma unroll
        for (int j=0;j<4;j++){
            int gn = colBase + tx*4 + j;
            if (gn >= N) continue;
            float v = acc[i][j];
            if (bias) v += bias[gn];
            if (act == 1) v = fmaxf(v, 0.f);
            if (Res) v += Res[(long long)gm*N + gn];
            Cb[(long long)gm*N + gn] = v;
        }
    }
}

/* ------------------------- elementwise / fused --------------------------- */
__global__ void build_hcat_k(const float* __restrict__ x, const float* __restrict__ W_in,
                             const float* __restrict__ b_in, const float* __restrict__ adp,
                             float* __restrict__ out)
{
    long long idx = (long long)blockIdx.x*blockDim.x + threadIdx.x;
    if (idx >= (long long)MM*DD) return;
    int d = (int)(idx % DD);
    long long tn = idx / DD;          /* t*NN + n (t-major) */
    int n = (int)(tn % NN);
    int t = (int)(tn / NN);
    float v;
    if (d < 24){
        const float* xr = x + ((long long)n*TT + t)*3;
        v = b_in[d] + xr[0]*W_in[d] + xr[1]*W_in[24+d] + xr[2]*W_in[48+d];
    } else {
        v = adp[tn*80 + (d-24)];
    }
    out[idx] = v;
}

__global__ void softmax_k(float* __restrict__ g)
{
    long long row = (long long)blockIdx.x*4 + (threadIdx.x>>5);
    if (row >= MM) return;
    int lane = threadIdx.x & 31;
    float* p = g + row*NN;
    float r[13];
    float mx = -3.4e38f;
    #pragma unroll
    for (int i=0;i<13;i++){ int j=lane+i*32; r[i] = (j<NN)? p[j] : -3.4e38f; mx = fmaxf(mx, r[i]); }
    #pragma unroll
    for (int o=16;o;o>>=1) mx = fmaxf(mx, __shfl_xor_sync(0xffffffffu, mx, o));
    float s = 0.f;
    #pragma unroll
    for (int i=0;i<13;i++){ int j=lane+i*32; if (j<NN){ r[i]=expf(r[i]-mx); s+=r[i]; } }
    #pragma unroll
    for (int o=16;o;o>>=1) s += __shfl_xor_sync(0xffffffffu, s, o);
    float inv = 1.f/s;
    #pragma unroll
    for (int i=0;i<13;i++){ int j=lane+i*32; if (j<NN) p[j] = r[i]*inv; }
}

/* kvs[b,h,m,d] = sum_l kn[l,m]*v[l,d] ; ksum[b,h,m] = sum_l kn[l,m] */
__global__ void attn_kvs_k(const float* __restrict__ qkv, float* __restrict__ kvs,
                           float* __restrict__ ksum, int L, int spatial)
{
    int b = blockIdx.x, h = blockIdx.y;
    __shared__ float sk[32][27];
    __shared__ float sv[32][27];
    __shared__ float ss[32];
    int tid = threadIdx.x;
    int mi[3], di[3]; bool ok[3];
    #pragma unroll
    for (int i=0;i<3;i++){ int p=tid+i*256; ok[i]=(p<676); mi[i]=p/26; di[i]=p-26*(p/26); }
    float acc[3] = {0.f,0.f,0.f};
    float asum = 0.f;
    for (int l0=0; l0<L; l0+=32){
        int lc = min(32, L-l0);
        for (int idx=tid; idx<lc*26; idx+=256){
            int r = idx/26, c = idx-r*26;
            int l = l0 + r;
            long long base = spatial ? ((long long)b*NN + l)*QKVW : ((long long)l*NN + b)*QKVW;
            sk[r][c] = qkv[base + DD   + h*HD + c];
            sv[r][c] = qkv[base + 2*DD + h*HD + c];
        }
        __syncthreads();
        if (tid < lc){
            float s=0.f;
            #pragma unroll
            for (int c=0;c<26;c++){ float k=sk[tid][c]; s += k*k; }
            ss[tid] = 1.f/fmaxf(sqrtf(s), 1e-12f);
        }
        __syncthreads();
        for (int idx=tid; idx<lc*26; idx+=256){
            int r = idx/26, c = idx-r*26;
            sk[r][c] *= ss[r];
        }
        __syncthreads();
        for (int l=0;l<lc;l++){
            #pragma unroll
            for (int i=0;i<3;i++)
                if (ok[i]) acc[i] += sk[l][mi[i]]*sv[l][di[i]];
        }
        if (tid < 26){
            for (int l=0;l<lc;l++) asum += sk[l][tid];
        }
        __syncthreads();
    }
    long long ob = ((long long)b*HH + h);
    #pragma unroll
    for (int i=0;i<3;i++){ int p=tid+i*256; if (p<676) kvs[ob*676 + p] = acc[i]; }
    if (tid<26) ksum[ob*26 + tid] = asum;
}

/* out = (qn@kvs + L*v) / (qn.ksum + L) ; one warp per (b,h,l) */
__global__ void attn_out_k(const float* __restrict__ qkv, const float* __restrict__ kvs,
                           const float* __restrict__ ksum, float* __restrict__ cat,
                           int L, int spatial)
{
    int b = blockIdx.x, h = blockIdx.y;
    int warp = threadIdx.x >> 5, lane = threadIdx.x & 31;
    __shared__ float skv[676];
    __shared__ float sks[26];
    long long ob = ((long long)b*HH + h);
    for (int idx=threadIdx.x; idx<676; idx+=128) skv[idx] = kvs[ob*676+idx];
    if (threadIdx.x < 26) sks[threadIdx.x] = ksum[ob*26+threadIdx.x];
    __syncthreads();
    int l = blockIdx.z*4 + warp;
    if (l >= L) return;
    long long base = spatial ? ((long long)b*NN + l)*QKVW : ((long long)l*NN + b)*QKVW;
    float q = (lane < 26) ? qkv[base + h*HD + lane] : 0.f;
    float sq = q*q;
    #pragma unroll
    for (int o=16;o;o>>=1) sq += __shfl_xor_sync(0xffffffffu, sq, o);
    float qn = q * (1.f/fmaxf(sqrtf(sq), 1e-12f));
    float dp = (lane<26) ? qn*sks[lane] : 0.f;
    #pragma unroll
    for (int o=16;o;o>>=1) dp += __shfl_xor_sync(0xffffffffu, dp, o);
    float den = dp + (float)L;
    float num = 0.f;
    #pragma unroll
    for (int m=0;m<26;m++){
        float qm = __shfl_sync(0xffffffffu, qn, m);
        if (lane < 26) num += qm * skv[m*26 + lane];
    }
    if (lane < 26){
        float v = qkv[base + 2*DD + h*HD + lane];
        float o = (num + (float)L * v)/den;
        long long cb = spatial ? ((long long)b*NN + l)*CATW + h*HD
                               : ((long long)l*NN + b)*CATW + DD + h*HD;
        cat[cb + lane] = o;
    }
}

/* h1 = LN(2*(h + a0*pw0 + 0.01*a1*pw1)) */
__global__ void combine_ln1_k(const float* __restrict__ h, const float* __restrict__ a0,
                              const float* __restrict__ pw0, const float* __restrict__ a1,
                              const float* __restrict__ pw1, const float* __restrict__ gam,
                              const float* __restrict__ bet, float* __restrict__ out)
{
    long long row = (long long)blockIdx.x*4 + (threadIdx.x>>5);
    if (row >= MM) return;
    int lane = threadIdx.x & 31;
    long long base = row*DD;
    float v[4]; float s = 0.f;
    #pragma unroll
    for (int i=0;i<4;i++){
        int j = lane + i*32;
        if (j < DD){
            float x = 2.f*(h[base+j] + a0[base+j]*pw0[base+j] + 0.01f*a1[base+j]*pw1[base+j]);
            v[i]=x; s+=x;
        } else v[i]=0.f;
    }
    #pragma unroll
    for (int o=16;o;o>>=1) s += __shfl_xor_sync(0xffffffffu, s, o);
    float mean = s * (1.f/DD);
    float vs = 0.f;
    #pragma unroll
    for (int i=0;i<4;i++){ int j=lane+i*32; if (j<DD){ float d=v[i]-mean; vs += d*d; } }
    #pragma unroll
    for (int o=16;o;o>>=1) vs += __shfl_xor_sync(0xffffffffu, vs, o);
    float inv = rsqrtf(vs*(1.f/DD) + 1e-5f);
    #pragma unroll
    for (int i=0;i<4;i++){ int j=lane+i*32; if (j<DD) out[base+j] = (v[i]-mean)*inv*gam[j] + bet[j]; }
}

__global__ void ln_k(const float* __restrict__ in, const float* __restrict__ gam,
                     const float* __restrict__ bet, float* __restrict__ out)
{
    long long row = (long long)blockIdx.x*4 + (threadIdx.x>>5);
    if (row >= MM) return;
    int lane = threadIdx.x & 31;
    const float* p = in + row*DD;
    float v[4]; float s = 0.f;
    #pragma unroll
    for (int i=0;i<4;i++){ int j=lane+i*32; v[i] = (j<DD)? p[j] : 0.f; s += v[i]; }
    #pragma unroll
    for (int o=16;o;o>>=1) s += __shfl_xor_sync(0xffffffffu, s, o);
    float mean = s * (1.f/DD);
    float vs = 0.f;
    #pragma unroll
    for (int i=0;i<4;i++){ int j=lane+i*32; if (j<DD){ float d=v[i]-mean; vs += d*d; } }
    #pragma unroll
    for (int o=16;o;o>>=1) vs += __shfl_xor_sync(0xffffffffu, vs, o);
    float inv = rsqrtf(vs*(1.f/DD) + 1e-5f);
    float* q = out + row*DD;
    #pragma unroll
    for (int i=0;i<4;i++){ int j=lane+i*32; if (j<DD) q[j] = (v[i]-mean)*inv*gam[j] + bet[j]; }
}

/* h2 [T,N,D] -> h2T [N, T*D] */
__global__ void transpose_k(const float* __restrict__ in, float* __restrict__ out)
{
    long long idx = (long long)blockIdx.x*blockDim.x + threadIdx.x;
    if (idx >= (long long)MM*DD) return;
    int d = (int)(idx % DD);
    long long tn = idx / DD;
    int n = (int)(tn % NN);
    int t = (int)(tn / NN);
    out[(long long)n*(TT*DD) + (long long)t*DD + d] = in[idx];
}

__global__ void ep_reduce_k(const float* __restrict__ part, const float* __restrict__ ep_b,
                            float* __restrict__ y)
{
    int idx = blockIdx.x*blockDim.x + threadIdx.x;
    if (idx >= NN*DD) return;
    float s = ep_b[idx % DD];
    #pragma unroll
    for (int j=0;j<EPK_SPLIT;j++) s += part[(long long)j*(NN*DD) + idx];
    y[idx] = s;
}

/* ------------------------------ host side -------------------------------- */
static void gemm(const float*A,const float*B,const float*bias,const float*Res,float*C,
                 int M,int N,int K,long long sA,long long sB,long long sC,
                 int transB,int act,int kChunk,int batch)
{
    dim3 grid((N+63)/64, (M+63)/64, batch);
    gemm_k<<<grid, 256>>>(A,B,bias,Res,C,M,N,K,sA,sB,sC,transB,act,kChunk);
}

static void gemm_tf(const float*A,const float*B,const float*bias,const float*Res,float*C,
                    int M,int N,int K,long long sA,long long sB,long long sC,
                    int transB,int act,int kChunk,int batch)
{
    dim3 grid((N+63)/64, (M+127)/128, batch);
    gemm_tf32_k<<<grid, 256>>>(A,B,bias,Res,C,M,N,K,sA,sB,sC,transB,act,kChunk);
}

extern "C" void kernel_launch(void* const* d_in, const int* in_sizes, int n_in,
                              void* d_out, int out_size)
{
    const float* x     = (const float*)d_in[0];
    const float* W_in  = (const float*)d_in[1];
    const float* b_in  = (const float*)d_in[2];
    const float* adp   = (const float*)d_in[3];
    const float* W_tp  = (const float*)d_in[4];
    const float* b_tp  = (const float*)d_in[5];
    const float* qkv_w = (const float*)d_in[6];
    const float* op_w  = (const float*)d_in[7];
    const float* op_b  = (const float*)d_in[8];
    const float* pw_w  = (const float*)d_in[9];
    const float* pw_b  = (const float*)d_in[10];
    const float* fc_w1 = (const float*)d_in[11];
    const float* fc_b1 = (const float*)d_in[12];
    const float* fc_w2 = (const float*)d_in[13];
    const float* fc_b2 = (const float*)d_in[14];
    const float* ln1_g = (const float*)d_in[15];
    const float* ln1_b = (const float*)d_in[16];
    const float* ln2_g = (const float*)d_in[17];
    const float* ln2_b = (const float*)d_in[18];
    const float* ep_w  = (const float*)d_in[19];
    const float* ep_b  = (const float*)d_in[20];
    const float* enc_w1= (const float*)d_in[21];
    const float* enc_b1= (const float*)d_in[22];
    const float* enc_w2= (const float*)d_in[23];
    const float* enc_b2= (const float*)d_in[24];
    const float* out_w = (const float*)d_in[25];
    const float* out_b = (const float*)d_in[26];
    float* out = (float*)d_out;

    float *hcat,*h,*graph,*z1,*qkv,*kvs,*ksum,*cat,*att0,*att1,*pw0,*pw1,*h1,*mid,*tmp,*h2,*h2T,*part,*y,*ymid;
    cudaGetSymbolAddress((void**)&hcat, g_hcat);
    cudaGetSymbolAddress((void**)&h,    g_h);
    cudaGetSymbolAddress((void**)&graph,g_graph);
    cudaGetSymbolAddress((void**)&z1,   g_z1);
    cudaGetSymbolAddress((void**)&qkv,  g_qkv);
    cudaGetSymbolAddress((void**)&kvs,  g_kvs);
    cudaGetSymbolAddress((void**)&ksum, g_ksum);
    cudaGetSymbolAddress((void**)&cat,  g_cat);
    cudaGetSymbolAddress((void**)&att0, g_att0);
    cudaGetSymbolAddress((void**)&att1, g_att1);
    cudaGetSymbolAddress((void**)&pw0,  g_pw0);
    cudaGetSymbolAddress((void**)&pw1,  g_pw1);
    cudaGetSymbolAddress((void**)&h1,   g_h1);
    cudaGetSymbolAddress((void**)&mid,  g_mid);
    cudaGetSymbolAddress((void**)&tmp,  g_tmp);
    cudaGetSymbolAddress((void**)&h2,   g_h2);
    cudaGetSymbolAddress((void**)&h2T,  g_h2T);
    cudaGetSymbolAddress((void**)&part, g_part);
    cudaGetSymbolAddress((void**)&y,    g_y);
    cudaGetSymbolAddress((void**)&ymid, g_ymid);

    const long long tot = (long long)MM*DD;

    /* 1. hcat = [x@W_in + b_in, adp]  -> [T,N,104] */
    build_hcat_k<<<(unsigned)((tot+255)/256), 256>>>(x, W_in, b_in, adp, hcat);

    /* 2. h = hcat @ W_tp + b_tp */
    gemm_tf(hcat, W_tp, b_tp, nullptr, h, MM, DD, DD, 0,0,0, 0,0,0, 1);

    /* 3. graph = relu(adp_t @ adp_t^T), batched over t */
    gemm_tf(adp, adp, nullptr, nullptr, graph, NN, NN, 80,
            (long long)NN*80, (long long)NN*80, (long long)NN*NN, 1, 1, 0, TT);

    /* 4. softmax rows */
    softmax_k<<<(MM+3)/4, 128>>>(graph);

    /* 5. z1 = graph @ h_t, batched over t */
    gemm_tf(graph, h, nullptr, nullptr, z1, NN, DD, NN,
            (long long)NN*NN, (long long)NN*DD, (long long)NN*DD, 0, 0, 0, TT);

    /* 6. att0 = fast_attn(h, weights[0]) */
    gemm_tf(h, qkv_w, nullptr, nullptr, qkv, MM, QKVW, DD, 0,0,0, 0,0,0, 1);
    attn_kvs_k<<<dim3(TT,HH), 256>>>(qkv, kvs, ksum, NN, 1);
    attn_out_k<<<dim3(TT,HH,(NN+3)/4), 128>>>(qkv, kvs, ksum, cat, NN, 1);
    attn_kvs_k<<<dim3(NN,HH), 256>>>(qkv, kvs, ksum, TT, 0);
    attn_out_k<<<dim3(NN,HH,(TT+3)/4), 128>>>(qkv, kvs, ksum, cat, TT, 0);
    gemm_tf(cat, op_w, op_b, nullptr, att0, MM, DD, CATW, 0,0,0, 0,0,0, 1);

    /* 7. att1 = fast_attn(z1, weights[1]) */
    gemm_tf(z1, qkv_w + DD*QKVW, nullptr, nullptr, qkv, MM, QKVW, DD, 0,0,0, 0,0,0, 1);
    attn_kvs_k<<<dim3(TT,HH), 256>>>(qkv, kvs, ksum, NN, 1);
    attn_out_k<<<dim3(TT,HH,(NN+3)/4), 128>>>(qkv, kvs, ksum, cat, NN, 1);
    attn_kvs_k<<<dim3(NN,HH), 256>>>(qkv, kvs, ksum, TT, 0);
    attn_out_k<<<dim3(NN,HH,(TT+3)/4), 128>>>(qkv, kvs, ksum, cat, TT, 0);
    gemm_tf(cat, op_w + CATW*DD, op_b + DD, nullptr, att1, MM, DD, CATW, 0,0,0, 0,0,0, 1);

    /* 8. pw projections */
    gemm_tf(h,    pw_w,         pw_b,      nullptr, pw0, MM, DD, DD, 0,0,0, 0,0,0, 1);
    gemm_tf(att0, pw_w + DD*DD, pw_b + DD, nullptr, pw1, MM, DD, DD, 0,0,0, 0,0,0, 1);

    /* 9. h1 = LN(2*(h + att0*pw0 + 0.01*att1*pw1)) */
    combine_ln1_k<<<(MM+3)/4, 128>>>(h, att0, pw0, att1, pw1, ln1_g, ln1_b, h1);

    /* 10. h2 = LN(h1 + MLP(h1)) */
    gemm_tf(h1,  fc_w1, fc_b1, nullptr, mid, MM, CATW, DD,  0,0,0, 0,1,0, 1);
    gemm_tf(mid, fc_w2, fc_b2, h1,      tmp, MM, DD, CATW,  0,0,0, 0,0,0, 1);
    ln_k<<<(MM+3)/4, 128>>>(tmp, ln2_g, ln2_b, h2);

    /* 11. encoder_proj: y = reshape(h2) @ ep_w + ep_b  (split-K, deterministic) */
    transpose_k<<<(unsigned)((tot+255)/256), 256>>>(h2, h2T);
    gemm_tf(h2T, ep_w, nullptr, nullptr, part, NN, DD, TT*DD,
            0, 0, (long long)NN*DD, 0, 0, EPK_CHUNK, EPK_SPLIT);
    ep_reduce_k<<<(NN*DD+255)/256, 256>>>(part, ep_b, y);

    /* 12. three residual MLP blocks (small; fp32) */
    for (int i=0;i<3;i++){
        gemm(y,    enc_w1 + (long long)i*DD*CATW, enc_b1 + i*CATW, nullptr, ymid, NN, CATW, DD, 0,0,0, 0,1,0, 1);
        gemm(ymid, enc_w2 + (long long)i*CATW*DD, enc_b2 + i*DD,   y,       y,    NN, DD, CATW, 0,0,0, 0,0,0, 1);
    }

    /* 13. out = y @ out_w + out_b -> [N,365] == d_out layout */
    gemm(y, out_w, out_b, nullptr, out, NN, TT, DD, 0,0,0, 0,0,0, 1);
}

// round 6
// speedup vs baseline: 1.5926x; 1.1465x over previous
#include <cuda_runtime.h>
#include <math.h>
#include <stdint.h>

#define TT 365
#define NN 400
#define DD 104
#define MM (TT*NN)        /* 146000 */
#define HH 4
#define HD 26
#define QKVW 312
#define CATW 208
#define EPK_CHUNK 1040    /* divisible by 16 */
#define EPK_SPLIT 37      /* 37*1040 >= 37960 */

/* ------------ scratch (device globals; no allocs in kernel_launch) ------- */
__device__ float g_hcat[MM*DD];
__device__ float g_h   [MM*DD];
__device__ float g_graph[TT*NN*NN];
__device__ float g_z1  [MM*DD];
__device__ float g_qkv [MM*QKVW];
__device__ float g_kvs [NN*HH*HD*HD];
__device__ float g_ksum[NN*HH*HD];
__device__ float g_cat [MM*CATW];
__device__ float g_att0[MM*DD];
__device__ float g_att1[MM*DD];
__device__ float g_pw0 [MM*DD];
__device__ float g_pw1 [MM*DD];
__device__ float g_h1  [MM*DD];
__device__ float g_mid [MM*CATW];
__device__ float g_tmp [MM*DD];
__device__ float g_h2  [MM*DD];
__device__ float g_h2T [MM*DD];
__device__ float g_part[EPK_SPLIT*NN*DD];
__device__ float g_y   [NN*DD];
__device__ float g_ymid[NN*CATW];

/* ----------------------- tf32 tensor-core GEMM --------------------------- */
__device__ __forceinline__ uint32_t f2tf32(float v){
    uint32_t u; asm("cvt.rna.tf32.f32 %0, %1;" : "=r"(u) : "f"(v)); return u;
}

/* C[M,N] = act(A[M,K] @ B) + bias (+Res). TRANSB: B is [N,K].
   Batched via blockIdx.z (strides). kChunk>0: blockIdx.z selects K-range.
   Tile 128x64x16, 256 threads, 8 warps of 32x32 (m16n8k8 tf32 mma).
   Double-buffered smem, float4 LDG + STS.128, one sync per k-iter.
   Smem layouts (32-bit words):
     As[m][k] stride 20  -> frag addr (grp*20+qid)%32 hits all 32 banks
     Bs[k][n] stride 72  -> frag addr (qid*8+grp)%32 hits all 32 banks
     Bs[n][k] stride 20 (TRANSB) -> same property as As. */
template<int TRANSB>
__global__ void __launch_bounds__(256,2)
gemm_tf32_k(const float* __restrict__ A, const float* __restrict__ B,
            const float* __restrict__ bias, const float* __restrict__ Res,
            float* __restrict__ C,
            int M, int N, int K,
            long long sA, long long sB, long long sC,
            int act, int kChunk)
{
    const int bz = blockIdx.z;
    const float* Ab = A + (long long)bz * sA;
    const float* Bb = B + (long long)bz * sB;
    float* Cb = C + (long long)bz * sC;
    int k0 = 0, k1 = K;
    if (kChunk > 0){ k0 = bz*kChunk; k1 = min(K, k0 + kChunk); }

    __shared__ uint32_t As[2][2560];   /* 128 rows * stride 20 */
    __shared__ uint32_t Bs[2][1280];   /* 16*72=1152 or 64*20=1280 */

    const int tid  = threadIdx.x;
    const int lane = tid & 31;
    const int warp = tid >> 5;
    const int warpM = warp & 3;
    const int warpN = warp >> 2;
    const int grp = lane >> 2;         /* 0..7 */
    const int qid = lane & 3;          /* 0..3 */
    const int rowBase = blockIdx.y * 128;
    const int colBase = blockIdx.x * 64;

    /* load-thread mapping */
    const int aM = tid >> 2;           /* 0..63 (+64 on 2nd) */
    const int aK = (tid & 3) * 4;
    const int bKn = tid >> 4;          /* normal: k 0..15 */
    const int bNn = (tid & 15) * 4;    /* normal: n 0,4,..60 */
    const int bNt = tid >> 2;          /* transB: n 0..63 */
    const int bKt = (tid & 3) * 4;     /* transB: k 0,4,8,12 */

    float4 aR[2]; float4 bR;
    const float4 z4 = make_float4(0.f,0.f,0.f,0.f);

    float c[2][4][4];
    #pragma unroll
    for (int i=0;i<2;i++)
        #pragma unroll
        for (int j=0;j<4;j++)
            #pragma unroll
            for (int r=0;r<4;r++) c[i][j][r]=0.f;

    /* ---- prologue: load tile k0 into regs, store to stage 0 ---- */
    {
        int kk = k0;
        #pragma unroll
        for (int i=0;i<2;i++){
            int gm = rowBase + aM + i*64, gk = kk + aK;
            aR[i] = (gm < M && gk < k1)
                  ? *reinterpret_cast<const float4*>(Ab + (long long)gm*K + gk) : z4;
        }
        if (!TRANSB){
            int gk = kk + bKn, gn = colBase + bNn;
            bR = (gk < k1 && gn < N)
               ? *reinterpret_cast<const float4*>(Bb + (long long)gk*N + gn) : z4;
        } else {
            int gn = colBase + bNt, gk = kk + bKt;
            bR = (gn < N && gk < k1)
               ? *reinterpret_cast<const float4*>(Bb + (long long)gn*K + gk) : z4;
        }
        #pragma unroll
        for (int i=0;i<2;i++){
            uint4 u = make_uint4(f2tf32(aR[i].x), f2tf32(aR[i].y),
                                 f2tf32(aR[i].z), f2tf32(aR[i].w));
            *reinterpret_cast<uint4*>(&As[0][(aM + i*64)*20 + aK]) = u;
        }
        {
            uint4 u = make_uint4(f2tf32(bR.x), f2tf32(bR.y),
                                 f2tf32(bR.z), f2tf32(bR.w));
            if (!TRANSB) *reinterpret_cast<uint4*>(&Bs[0][bKn*72 + bNn]) = u;
            else         *reinterpret_cast<uint4*>(&Bs[0][bNt*20 + bKt]) = u;
        }
    }
    __syncthreads();

    int stage = 0;
    for (int kk = k0; kk < k1; kk += 16){
        const bool haveNext = (kk + 16) < k1;
        if (haveNext){
            int kn = kk + 16;
            #pragma unroll
            for (int i=0;i<2;i++){
                int gm = rowBase + aM + i*64, gk = kn + aK;
                aR[i] = (gm < M && gk < k1)
                      ? *reinterpret_cast<const float4*>(Ab + (long long)gm*K + gk) : z4;
            }
            if (!TRANSB){
                int gk = kn + bKn, gn = colBase + bNn;
                bR = (gk < k1 && gn < N)
                   ? *reinterpret_cast<const float4*>(Bb + (long long)gk*N + gn) : z4;
            } else {
                int gn = colBase + bNt, gk = kn + bKt;
                bR = (gn < N && gk < k1)
                   ? *reinterpret_cast<const float4*>(Bb + (long long)gn*K + gk) : z4;
            }
        }

        /* ---- MMA on current stage ---- */
        const uint32_t* Ac = As[stage];
        const uint32_t* Bc = Bs[stage];
        #pragma unroll
        for (int kb=0; kb<16; kb+=8){
            uint32_t a[2][4], b[4][2];
            #pragma unroll
            for (int mt=0;mt<2;mt++){
                int r = warpM*32 + mt*16 + grp;
                a[mt][0] = Ac[(r  )*20 + kb + qid];
                a[mt][1] = Ac[(r+8)*20 + kb + qid];
                a[mt][2] = Ac[(r  )*20 + kb + qid + 4];
                a[mt][3] = Ac[(r+8)*20 + kb + qid + 4];
            }
            #pragma unroll
            for (int nt=0;nt<4;nt++){
                int cn = warpN*32 + nt*8 + grp;
                if (!TRANSB){
                    b[nt][0] = Bc[(kb+qid  )*72 + cn];
                    b[nt][1] = Bc[(kb+qid+4)*72 + cn];
                } else {
                    b[nt][0] = Bc[cn*20 + kb + qid];
                    b[nt][1] = Bc[cn*20 + kb + qid + 4];
                }
            }
            #pragma unroll
            for (int mt=0;mt<2;mt++){
                #pragma unroll
                for (int nt=0;nt<4;nt++){
                    asm("mma.sync.aligned.m16n8k8.row.col.f32.tf32.tf32.f32 "
                        "{%0,%1,%2,%3}, {%4,%5,%6,%7}, {%8,%9}, {%0,%1,%2,%3};"
                        : "+f"(c[mt][nt][0]), "+f"(c[mt][nt][1]),
                          "+f"(c[mt][nt][2]), "+f"(c[mt][nt][3])
                        : "r"(a[mt][0]), "r"(a[mt][1]), "r"(a[mt][2]), "r"(a[mt][3]),
                          "r"(b[nt][0]), "r"(b[nt][1]));
                }
            }
        }

        if (haveNext){
            int st = stage ^ 1;
            #pragma unroll
            for (int i=0;i<2;i++){
                uint4 u = make_uint4(f2tf32(aR[i].x), f2tf32(aR[i].y),
                                     f2tf32(aR[i].z), f2tf32(aR[i].w));
                *reinterpret_cast<uint4*>(&As[st][(aM + i*64)*20 + aK]) = u;
            }
            uint4 u = make_uint4(f2tf32(bR.x), f2tf32(bR.y),
                                 f2tf32(bR.z), f2tf32(bR.w));
            if (!TRANSB) *reinterpret_cast<uint4*>(&Bs[st][bKn*72 + bNn]) = u;
            else         *reinterpret_cast<uint4*>(&Bs[st][bNt*20 + bKt]) = u;
            __syncthreads();
            stage = st;
        }
    }

    /* ---- epilogue ---- */
    #pragma unroll
    for (int mt=0;mt<2;mt++){
        #pragma unroll
        for (int nt=0;nt<4;nt++){
            int row0 = rowBase + warpM*32 + mt*16 + grp;
            int col0 = colBase + warpN*32 + nt*8 + qid*2;
            #pragma unroll
            for (int r=0;r<4;r++){
                int row = row0 + (r>>1)*8;
                int col = col0 + (r&1);
                if (row < M && col < N){
                    float v = c[mt][nt][r];
                    if (bias) v += bias[col];
                    if (act == 1) v = fmaxf(v, 0.f);
                    if (Res) v += Res[(long long)row*N + col];
                    Cb[(long long)row*N + col] = v;
                }
            }
        }
    }
}

/* --------------------------- fp32 GEMM (small) ---------------------------- */
__global__ void gemm_k(const float* __restrict__ A, const float* __restrict__ B,
                       const float* __restrict__ bias, const float* __restrict__ Res,
                       float* __restrict__ C,
                       int M, int N, int K,
                       long long sA, long long sB, long long sC,
                       int transB, int act, int kChunk)
{
    const int bz = blockIdx.z;
    const float* Ab = A + (long long)bz * sA;
    const float* Bb = B + (long long)bz * sB;
    float* Cb = C + (long long)bz * sC;
    int k0 = 0, k1 = K;
    if (kChunk > 0){ k0 = bz*kChunk; k1 = min(K, k0 + kChunk); }

    __shared__ float Ast[16][68];
    __shared__ float Bs [16][68];

    const int tid = threadIdx.x;
    const int tx = tid & 15, ty = tid >> 4;
    const int rowBase = blockIdx.y * 64;
    const int colBase = blockIdx.x * 64;

    float acc[4][4];
    #pragma unroll
    for (int i=0;i<4;i++){
        #pragma unroll
        for (int j=0;j<4;j++) acc[i][j]=0.f;
    }

    for (int kk = k0; kk < k1; kk += 16){
        #pragma unroll
        for (int i=0;i<4;i++){
            int idx = tid + i*256;
            int m = idx >> 4, kq = idx & 15;
            int gm = rowBase + m, gk = kk + kq;
            float v = 0.f;
            if (gm < M && gk < k1) v = Ab[(long long)gm*K + gk];
            Ast[kq][m] = v;
        }
        #pragma unroll
        for (int i=0;i<4;i++){
            int idx = tid + i*256;
            int kq = idx >> 6, n = idx & 63;
            int gk = kk + kq, gn = colBase + n;
            float v = 0.f;
            if (gn < N && gk < k1)
                v = transB ? Bb[(long long)gn*K + gk] : Bb[(long long)gk*N + gn];
            Bs[kq][n] = v;
        }
        __syncthreads();
        #pragma unroll
        for (int kq=0;kq<16;kq++){
            float4 av = *reinterpret_cast<const float4*>(&Ast[kq][ty*4]);
            float4 bv = *reinterpret_cast<const float4*>(&Bs [kq][tx*4]);
            float am[4] = {av.x,av.y,av.z,av.w};
            float bn[4] = {bv.x,bv.y,bv.z,bv.w};
            #pragma unroll
            for (int i=0;i<4;i++){
                #pragma unroll
                for (int j=0;j<4;j++) acc[i][j] += am[i]*bn[j];
            }
        }
        __syncthreads();
    }
    #pragma unroll
    for (int i=0;i<4;i++){
        int gm = rowBase + ty*4 + i;
        if (gm >= M) continue;
        #pragma unroll
        for (int j=0;j<4;j++){
            int gn = colBase + tx*4 + j;
            if (gn >= N) continue;
            float v = acc[i][j];
            if (bias) v += bias[gn];
            if (act == 1) v = fmaxf(v, 0.f);
            if (Res) v += Res[(long long)gm*N + gn];
            Cb[(long long)gm*N + gn] = v;
        }
    }
}

/* ------------------------- elementwise / fused --------------------------- */
__global__ void build_hcat_k(const float* __restrict__ x, const float* __restrict__ W_in,
                             const float* __restrict__ b_in, const float* __restrict__ adp,
                             float* __restrict__ out)
{
    long long idx = (long long)blockIdx.x*blockDim.x + threadIdx.x;
    if (idx >= (long long)MM*DD) return;
    int d = (int)(idx % DD);
    long long tn = idx / DD;          /* t*NN + n (t-major) */
    int n = (int)(tn % NN);
    int t = (int)(tn / NN);
    float v;
    if (d < 24){
        const float* xr = x + ((long long)n*TT + t)*3;
        v = b_in[d] + xr[0]*W_in[d] + xr[1]*W_in[24+d] + xr[2]*W_in[48+d];
    } else {
        v = adp[tn*80 + (d-24)];
    }
    out[idx] = v;
}

__global__ void softmax_k(float* __restrict__ g)
{
    long long row = (long long)blockIdx.x*4 + (threadIdx.x>>5);
    if (row >= MM) return;
    int lane = threadIdx.x & 31;
    float* p = g + row*NN;
    float r[13];
    float mx = -3.4e38f;
    #pragma unroll
    for (int i=0;i<13;i++){ int j=lane+i*32; r[i] = (j<NN)? p[j] : -3.4e38f; mx = fmaxf(mx, r[i]); }
    #pragma unroll
    for (int o=16;o;o>>=1) mx = fmaxf(mx, __shfl_xor_sync(0xffffffffu, mx, o));
    float s = 0.f;
    #pragma unroll
    for (int i=0;i<13;i++){ int j=lane+i*32; if (j<NN){ r[i]=expf(r[i]-mx); s+=r[i]; } }
    #pragma unroll
    for (int o=16;o;o>>=1) s += __shfl_xor_sync(0xffffffffu, s, o);
    float inv = 1.f/s;
    #pragma unroll
    for (int i=0;i<13;i++){ int j=lane+i*32; if (j<NN) p[j] = r[i]*inv; }
}

/* kvs[b,h,m,d] = sum_l kn[l,m]*v[l,d] ; ksum[b,h,m] = sum_l kn[l,m] */
__global__ void attn_kvs_k(const float* __restrict__ qkv, float* __restrict__ kvs,
                           float* __restrict__ ksum, int L, int spatial)
{
    int b = blockIdx.x, h = blockIdx.y;
    __shared__ float sk[32][27];
    __shared__ float sv[32][27];
    __shared__ float ss[32];
    int tid = threadIdx.x;
    int mi[3], di[3]; bool ok[3];
    #pragma unroll
    for (int i=0;i<3;i++){ int p=tid+i*256; ok[i]=(p<676); mi[i]=p/26; di[i]=p-26*(p/26); }
    float acc[3] = {0.f,0.f,0.f};
    float asum = 0.f;
    for (int l0=0; l0<L; l0+=32){
        int lc = min(32, L-l0);
        for (int idx=tid; idx<lc*26; idx+=256){
            int r = idx/26, c = idx-r*26;
            int l = l0 + r;
            long long base = spatial ? ((long long)b*NN + l)*QKVW : ((long long)l*NN + b)*QKVW;
            sk[r][c] = qkv[base + DD   + h*HD + c];
            sv[r][c] = qkv[base + 2*DD + h*HD + c];
        }
        __syncthreads();
        if (tid < lc){
            float s=0.f;
            #pragma unroll
            for (int c=0;c<26;c++){ float k=sk[tid][c]; s += k*k; }
            ss[tid] = 1.f/fmaxf(sqrtf(s), 1e-12f);
        }
        __syncthreads();
        for (int idx=tid; idx<lc*26; idx+=256){
            int r = idx/26, c = idx-r*26;
            sk[r][c] *= ss[r];
        }
        __syncthreads();
        for (int l=0;l<lc;l++){
            #pragma unroll
            for (int i=0;i<3;i++)
                if (ok[i]) acc[i] += sk[l][mi[i]]*sv[l][di[i]];
        }
        if (tid < 26){
            for (int l=0;l<lc;l++) asum += sk[l][tid];
        }
        __syncthreads();
    }
    long long ob = ((long long)b*HH + h);
    #pragma unroll
    for (int i=0;i<3;i++){ int p=tid+i*256; if (p<676) kvs[ob*676 + p] = acc[i]; }
    if (tid<26) ksum[ob*26 + tid] = asum;
}

/* out = (qn@kvs + L*v) / (qn.ksum + L) ; one warp per (b,h,l) */
__global__ void attn_out_k(const float* __restrict__ qkv, const float* __restrict__ kvs,
                           const float* __restrict__ ksum, float* __restrict__ cat,
                           int L, int spatial)
{
    int b = blockIdx.x, h = blockIdx.y;
    int warp = threadIdx.x >> 5, lane = threadIdx.x & 31;
    __shared__ float skv[676];
    __shared__ float sks[26];
    long long ob = ((long long)b*HH + h);
    for (int idx=threadIdx.x; idx<676; idx+=128) skv[idx] = kvs[ob*676+idx];
    if (threadIdx.x < 26) sks[threadIdx.x] = ksum[ob*26+threadIdx.x];
    __syncthreads();
    int l = blockIdx.z*4 + warp;
    if (l >= L) return;
    long long base = spatial ? ((long long)b*NN + l)*QKVW : ((long long)l*NN + b)*QKVW;
    float q = (lane < 26) ? qkv[base + h*HD + lane] : 0.f;
    float sq = q*q;
    #pragma unroll
    for (int o=16;o;o>>=1) sq += __shfl_xor_sync(0xffffffffu, sq, o);
    float qn = q * (1.f/fmaxf(sqrtf(sq), 1e-12f));
    float dp = (lane<26) ? qn*sks[lane] : 0.f;
    #pragma unroll
    for (int o=16;o;o>>=1) dp += __shfl_xor_sync(0xffffffffu, dp, o);
    float den = dp + (float)L;
    float num = 0.f;
    #pragma unroll
    for (int m=0;m<26;m++){
        float qm = __shfl_sync(0xffffffffu, qn, m);
        if (lane < 26) num += qm * skv[m*26 + lane];
    }
    if (lane < 26){
        float v = qkv[base + 2*DD + h*HD + lane];
        float o = (num + (float)L * v)/den;
        long long cb = spatial ? ((long long)b*NN + l)*CATW + h*HD
                               : ((long long)l*NN + b)*CATW + DD + h*HD;
        cat[cb + lane] = o;
    }
}

/* h1 = LN(2*(h + a0*pw0 + 0.01*a1*pw1)) */
__global__ void combine_ln1_k(const float* __restrict__ h, const float* __restrict__ a0,
                              const float* __restrict__ pw0, const float* __restrict__ a1,
                              const float* __restrict__ pw1, const float* __restrict__ gam,
                              const float* __restrict__ bet, float* __restrict__ out)
{
    long long row = (long long)blockIdx.x*4 + (threadIdx.x>>5);
    if (row >= MM) return;
    int lane = threadIdx.x & 31;
    long long base = row*DD;
    float v[4]; float s = 0.f;
    #pragma unroll
    for (int i=0;i<4;i++){
        int j = lane + i*32;
        if (j < DD){
            float x = 2.f*(h[base+j] + a0[base+j]*pw0[base+j] + 0.01f*a1[base+j]*pw1[base+j]);
            v[i]=x; s+=x;
        } else v[i]=0.f;
    }
    #pragma unroll
    for (int o=16;o;o>>=1) s += __shfl_xor_sync(0xffffffffu, s, o);
    float mean = s * (1.f/DD);
    float vs = 0.f;
    #pragma unroll
    for (int i=0;i<4;i++){ int j=lane+i*32; if (j<DD){ float d=v[i]-mean; vs += d*d; } }
    #pragma unroll
    for (int o=16;o;o>>=1) vs += __shfl_xor_sync(0xffffffffu, vs, o);
    float inv = rsqrtf(vs*(1.f/DD) + 1e-5f);
    #pragma unroll
    for (int i=0;i<4;i++){ int j=lane+i*32; if (j<DD) out[base+j] = (v[i]-mean)*inv*gam[j] + bet[j]; }
}

__global__ void ln_k(const float* __restrict__ in, const float* __restrict__ gam,
                     const float* __restrict__ bet, float* __restrict__ out)
{
    long long row = (long long)blockIdx.x*4 + (threadIdx.x>>5);
    if (row >= MM) return;
    int lane = threadIdx.x & 31;
    const float* p = in + row*DD;
    float v[4]; float s = 0.f;
    #pragma unroll
    for (int i=0;i<4;i++){ int j=lane+i*32; v[i] = (j<DD)? p[j] : 0.f; s += v[i]; }
    #pragma unroll
    for (int o=16;o;o>>=1) s += __shfl_xor_sync(0xffffffffu, s, o);
    float mean = s * (1.f/DD);
    float vs = 0.f;
    #pragma unroll
    for (int i=0;i<4;i++){ int j=lane+i*32; if (j<DD){ float d=v[i]-mean; vs += d*d; } }
    #pragma unroll
    for (int o=16;o;o>>=1) vs += __shfl_xor_sync(0xffffffffu, vs, o);
    float inv = rsqrtf(vs*(1.f/DD) + 1e-5f);
    float* q = out + row*DD;
    #pragma unroll
    for (int i=0;i<4;i++){ int j=lane+i*32; if (j<DD) q[j] = (v[i]-mean)*inv*gam[j] + bet[j]; }
}

/* h2 [T,N,D] -> h2T [N, T*D] */
__global__ void transpose_k(const float* __restrict__ in, float* __restrict__ out)
{
    long long idx = (long long)blockIdx.x*blockDim.x + threadIdx.x;
    if (idx >= (long long)MM*DD) return;
    int d = (int)(idx % DD);
    long long tn = idx / DD;
    int n = (int)(tn % NN);
    int t = (int)(tn / NN);
    out[(long long)n*(TT*DD) + (long long)t*DD + d] = in[idx];
}

__global__ void ep_reduce_k(const float* __restrict__ part, const float* __restrict__ ep_b,
                            float* __restrict__ y)
{
    int idx = blockIdx.x*blockDim.x + threadIdx.x;
    if (idx >= NN*DD) return;
    float s = ep_b[idx % DD];
    #pragma unroll
    for (int j=0;j<EPK_SPLIT;j++) s += part[(long long)j*(NN*DD) + idx];
    y[idx] = s;
}

/* ------------------------------ host side -------------------------------- */
static void gemm(const float*A,const float*B,const float*bias,const float*Res,float*C,
                 int M,int N,int K,long long sA,long long sB,long long sC,
                 int transB,int act,int kChunk,int batch)
{
    dim3 grid((N+63)/64, (M+63)/64, batch);
    gemm_k<<<grid, 256>>>(A,B,bias,Res,C,M,N,K,sA,sB,sC,transB,act,kChunk);
}

static void gemm_tf(const float*A,const float*B,const float*bias,const float*Res,float*C,
                    int M,int N,int K,long long sA,long long sB,long long sC,
                    int transB,int act,int kChunk,int batch)
{
    dim3 grid((N+63)/64, (M+127)/128, batch);
    if (transB) gemm_tf32_k<1><<<grid, 256>>>(A,B,bias,Res,C,M,N,K,sA,sB,sC,act,kChunk);
    else        gemm_tf32_k<0><<<grid, 256>>>(A,B,bias,Res,C,M,N,K,sA,sB,sC,act,kChunk);
}

extern "C" void kernel_launch(void* const* d_in, const int* in_sizes, int n_in,
                              void* d_out, int out_size)
{
    const float* x     = (const float*)d_in[0];
    const float* W_in  = (const float*)d_in[1];
    const float* b_in  = (const float*)d_in[2];
    const float* adp   = (const float*)d_in[3];
    const float* W_tp  = (const float*)d_in[4];
    const float* b_tp  = (const float*)d_in[5];
    const float* qkv_w = (const float*)d_in[6];
    const float* op_w  = (const float*)d_in[7];
    const float* op_b  = (const float*)d_in[8];
    const float* pw_w  = (const float*)d_in[9];
    const float* pw_b  = (const float*)d_in[10];
    const float* fc_w1 = (const float*)d_in[11];
    const float* fc_b1 = (const float*)d_in[12];
    const float* fc_w2 = (const float*)d_in[13];
    const float* fc_b2 = (const float*)d_in[14];
    const float* ln1_g = (const float*)d_in[15];
    const float* ln1_b = (const float*)d_in[16];
    const float* ln2_g = (const float*)d_in[17];
    const float* ln2_b = (const float*)d_in[18];
    const float* ep_w  = (const float*)d_in[19];
    const float* ep_b  = (const float*)d_in[20];
    const float* enc_w1= (const float*)d_in[21];
    const float* enc_b1= (const float*)d_in[22];
    const float* enc_w2= (const float*)d_in[23];
    const float* enc_b2= (const float*)d_in[24];
    const float* out_w = (const float*)d_in[25];
    const float* out_b = (const float*)d_in[26];
    float* out = (float*)d_out;

    float *hcat,*h,*graph,*z1,*qkv,*kvs,*ksum,*cat,*att0,*att1,*pw0,*pw1,*h1,*mid,*tmp,*h2,*h2T,*part,*y,*ymid;
    cudaGetSymbolAddress((void**)&hcat, g_hcat);
    cudaGetSymbolAddress((void**)&h,    g_h);
    cudaGetSymbolAddress((void**)&graph,g_graph);
    cudaGetSymbolAddress((void**)&z1,   g_z1);
    cudaGetSymbolAddress((void**)&qkv,  g_qkv);
    cudaGetSymbolAddress((void**)&kvs,  g_kvs);
    cudaGetSymbolAddress((void**)&ksum, g_ksum);
    cudaGetSymbolAddress((void**)&cat,  g_cat);
    cudaGetSymbolAddress((void**)&att0, g_att0);
    cudaGetSymbolAddress((void**)&att1, g_att1);
    cudaGetSymbolAddress((void**)&pw0,  g_pw0);
    cudaGetSymbolAddress((void**)&pw1,  g_pw1);
    cudaGetSymbolAddress((void**)&h1,   g_h1);
    cudaGetSymbolAddress((void**)&mid,  g_mid);
    cudaGetSymbolAddress((void**)&tmp,  g_tmp);
    cudaGetSymbolAddress((void**)&h2,   g_h2);
    cudaGetSymbolAddress((void**)&h2T,  g_h2T);
    cudaGetSymbolAddress((void**)&part, g_part);
    cudaGetSymbolAddress((void**)&y,    g_y);
    cudaGetSymbolAddress((void**)&ymid, g_ymid);

    const long long tot = (long long)MM*DD;

    /* 1. hcat = [x@W_in + b_in, adp]  -> [T,N,104] */
    build_hcat_k<<<(unsigned)((tot+255)/256), 256>>>(x, W_in, b_in, adp, hcat);

    /* 2. h = hcat @ W_tp + b_tp */
    gemm_tf(hcat, W_tp, b_tp, nullptr, h, MM, DD, DD, 0,0,0, 0,0,0, 1);

    /* 3. graph = relu(adp_t @ adp_t^T), batched over t */
    gemm_tf(adp, adp, nullptr, nullptr, graph, NN, NN, 80,
            (long long)NN*80, (long long)NN*80, (long long)NN*NN, 1, 1, 0, TT);

    /* 4. softmax rows */
    softmax_k<<<(MM+3)/4, 128>>>(graph);

    /* 5. z1 = graph @ h_t, batched over t */
    gemm_tf(graph, h, nullptr, nullptr, z1, NN, DD, NN,
            (long long)NN*NN, (long long)NN*DD, (long long)NN*DD, 0, 0, 0, TT);

    /* 6. att0 = fast_attn(h, weights[0]) */
    gemm_tf(h, qkv_w, nullptr, nullptr, qkv, MM, QKVW, DD, 0,0,0, 0,0,0, 1);
    attn_kvs_k<<<dim3(TT,HH), 256>>>(qkv, kvs, ksum, NN, 1);
    attn_out_k<<<dim3(TT,HH,(NN+3)/4), 128>>>(qkv, kvs, ksum, cat, NN, 1);
    attn_kvs_k<<<dim3(NN,HH), 256>>>(qkv, kvs, ksum, TT, 0);
    attn_out_k<<<dim3(NN,HH,(TT+3)/4), 128>>>(qkv, kvs, ksum, cat, TT, 0);
    gemm_tf(cat, op_w, op_b, nullptr, att0, MM, DD, CATW, 0,0,0, 0,0,0, 1);

    /* 7. att1 = fast_attn(z1, weights[1]) */
    gemm_tf(z1, qkv_w + DD*QKVW, nullptr, nullptr, qkv, MM, QKVW, DD, 0,0,0, 0,0,0, 1);
    attn_kvs_k<<<dim3(TT,HH), 256>>>(qkv, kvs, ksum, NN, 1);
    attn_out_k<<<dim3(TT,HH,(NN+3)/4), 128>>>(qkv, kvs, ksum, cat, NN, 1);
    attn_kvs_k<<<dim3(NN,HH), 256>>>(qkv, kvs, ksum, TT, 0);
    attn_out_k<<<dim3(NN,HH,(TT+3)/4), 128>>>(qkv, kvs, ksum, cat, TT, 0);
    gemm_tf(cat, op_w + CATW*DD, op_b + DD, nullptr, att1, MM, DD, CATW, 0,0,0, 0,0,0, 1);

    /* 8. pw projections */
    gemm_tf(h,    pw_w,         pw_b,      nullptr, pw0, MM, DD, DD, 0,0,0, 0,0,0, 1);
    gemm_tf(att0, pw_w + DD*DD, pw_b + DD, nullptr, pw1, MM, DD, DD, 0,0,0, 0,0,0, 1);

    /* 9. h1 = LN(2*(h + att0*pw0 + 0.01*att1*pw1)) */
    combine_ln1_k<<<(MM+3)/4, 128>>>(h, att0, pw0, att1, pw1, ln1_g, ln1_b, h1);

    /* 10. h2 = LN(h1 + MLP(h1)) */
    gemm_tf(h1,  fc_w1, fc_b1, nullptr, mid, MM, CATW, DD,  0,0,0, 0,1,0, 1);
    gemm_tf(mid, fc_w2, fc_b2, h1,      tmp, MM, DD, CATW,  0,0,0, 0,0,0, 1);
    ln_k<<<(MM+3)/4, 128>>>(tmp, ln2_g, ln2_b, h2);

    /* 11. encoder_proj: y = reshape(h2) @ ep_w + ep_b  (split-K, deterministic) */
    transpose_k<<<(unsigned)((tot+255)/256), 256>>>(h2, h2T);
    gemm_tf(h2T, ep_w, nullptr, nullptr, part, NN, DD, TT*DD,
            0, 0, (long long)NN*DD, 0, 0, EPK_CHUNK, EPK_SPLIT);
    ep_reduce_k<<<(NN*DD+255)/256, 256>>>(part, ep_b, y);

    /* 12. three residual MLP blocks (small; fp32) */
    for (int i=0;i<3;i++){
        gemm(y,    enc_w1 + (long long)i*DD*CATW, enc_b1 + i*CATW, nullptr, ymid, NN, CATW, DD, 0,0,0, 0,1,0, 1);
        gemm(ymid, enc_w2 + (long long)i*CATW*DD, enc_b2 + i*DD,   y,       y,    NN, DD, CATW, 0,0,0, 0,0,0, 1);
    }

    /* 13. out = y @ out_w + out_b -> [N,365] == d_out layout */
    gemm(y, out_w, out_b, nullptr, out, NN, TT, DD, 0,0,0, 0,0,0, 1);
}

// round 9
// speedup vs baseline: 1.6092x; 1.0104x over previous
#include <cuda_runtime.h>
#include <math.h>
#include <stdint.h>

#define TT 365
#define NN 400
#define DD 104
#define MM (TT*NN)        /* 146000 */
#define HH 4
#define HD 26
#define QKVW 312
#define CATW 208
#define EPK_CHUNK 1040    /* divisible by 16 */
#define EPK_SPLIT 37      /* 37*1040 >= 37960 */

/* ------------ scratch (device globals; no allocs in kernel_launch) ------- */
__device__ float g_hcat[MM*DD];
__device__ float g_h   [MM*DD];
__device__ float g_graph[TT*NN*NN];
__device__ float g_z1  [MM*DD];
__device__ float g_qkv [MM*QKVW];
__device__ float g_kvs [NN*HH*HD*HD];
__device__ float g_ksum[NN*HH*HD];
__device__ float g_cat [MM*CATW];
__device__ float g_att0[MM*DD];
__device__ float g_att1[MM*DD];
__device__ float g_pw0 [MM*DD];
__device__ float g_pw1 [MM*DD];
__device__ float g_h1  [MM*DD];
__device__ float g_mid [MM*CATW];
__device__ float g_tmp [MM*DD];
__device__ float g_h2  [MM*DD];
__device__ float g_h2T [MM*DD];
__device__ float g_part[EPK_SPLIT*NN*DD];
__device__ float g_y   [NN*DD];
__device__ float g_ymid[NN*CATW];

/* ----------------------- tf32 tensor-core GEMM --------------------------- */
__device__ __forceinline__ uint32_t f2tf32(float v){
    uint32_t u; asm("cvt.rna.tf32.f32 %0, %1;" : "=r"(u) : "f"(v)); return u;
}

/* C[M,N] = act(A[M,K] @ B) + bias (+Res). TRANSB: B is [N,K].
   Batched via blockIdx.z (strides). kChunk>0: blockIdx.z selects K-range.
   Tile 128x64x16, 256 threads, 8 warps of 32x32 (m16n8k8 tf32 mma).
   Double-buffered smem, float4 LDG + STS.128, one sync per k-iter.
   Smem layouts (32-bit words):
     As[m][k] stride 20  -> frag addr (grp*20+qid)%32 hits all 32 banks
     Bs[k][n] stride 72  -> frag addr (qid*8+grp)%32 hits all 32 banks
     Bs[n][k] stride 20 (TRANSB) -> same property as As. */
template<int TRANSB>
__global__ void __launch_bounds__(256,2)
gemm_tf32_k(const float* __restrict__ A, const float* __restrict__ B,
            const float* __restrict__ bias, const float* __restrict__ Res,
            float* __restrict__ C,
            int M, int N, int K,
            long long sA, long long sB, long long sC,
            int act, int kChunk)
{
    const int bz = blockIdx.z;
    const float* Ab = A + (long long)bz * sA;
    const float* Bb = B + (long long)bz * sB;
    float* Cb = C + (long long)bz * sC;
    int k0 = 0, k1 = K;
    if (kChunk > 0){ k0 = bz*kChunk; k1 = min(K, k0 + kChunk); }

    __shared__ uint32_t As[2][2560];   /* 128 rows * stride 20 */
    __shared__ uint32_t Bs[2][1280];   /* 16*72=1152 or 64*20=1280 */

    const int tid  = threadIdx.x;
    const int lane = tid & 31;
    const int warp = tid >> 5;
    const int warpM = warp & 3;
    const int warpN = warp >> 2;
    const int grp = lane >> 2;         /* 0..7 */
    const int qid = lane & 3;          /* 0..3 */
    const int rowBase = blockIdx.y * 128;
    const int colBase = blockIdx.x * 64;

    /* load-thread mapping */
    const int aM = tid >> 2;           /* 0..63 (+64 on 2nd) */
    const int aK = (tid & 3) * 4;
    const int bKn = tid >> 4;          /* normal: k 0..15 */
    const int bNn = (tid & 15) * 4;    /* normal: n 0,4,..60 */
    const int bNt = tid >> 2;          /* transB: n 0..63 */
    const int bKt = (tid & 3) * 4;     /* transB: k 0,4,8,12 */

    float4 aR[2]; float4 bR;
    const float4 z4 = make_float4(0.f,0.f,0.f,0.f);

    float c[2][4][4];
    #pragma unroll
    for (int i=0;i<2;i++)
        #pragma unroll
        for (int j=0;j<4;j++)
            #pragma unroll
            for (int r=0;r<4;r++) c[i][j][r]=0.f;

    /* ---- prologue: load tile k0 into regs, store to stage 0 ---- */
    {
        int kk = k0;
        #pragma unroll
        for (int i=0;i<2;i++){
            int gm = rowBase + aM + i*64, gk = kk + aK;
            aR[i] = (gm < M && gk < k1)
                  ? *reinterpret_cast<const float4*>(Ab + (long long)gm*K + gk) : z4;
        }
        if (!TRANSB){
            int gk = kk + bKn, gn = colBase + bNn;
            bR = (gk < k1 && gn < N)
               ? *reinterpret_cast<const float4*>(Bb + (long long)gk*N + gn) : z4;
        } else {
            int gn = colBase + bNt, gk = kk + bKt;
            bR = (gn < N && gk < k1)
               ? *reinterpret_cast<const float4*>(Bb + (long long)gn*K + gk) : z4;
        }
        #pragma unroll
        for (int i=0;i<2;i++){
            uint4 u = make_uint4(f2tf32(aR[i].x), f2tf32(aR[i].y),
                                 f2tf32(aR[i].z), f2tf32(aR[i].w));
            *reinterpret_cast<uint4*>(&As[0][(aM + i*64)*20 + aK]) = u;
        }
        {
            uint4 u = make_uint4(f2tf32(bR.x), f2tf32(bR.y),
                                 f2tf32(bR.z), f2tf32(bR.w));
            if (!TRANSB) *reinterpret_cast<uint4*>(&Bs[0][bKn*72 + bNn]) = u;
            else         *reinterpret_cast<uint4*>(&Bs[0][bNt*20 + bKt]) = u;
        }
    }
    __syncthreads();

    int stage = 0;
    for (int kk = k0; kk < k1; kk += 16){
        const bool haveNext = (kk + 16) < k1;
        if (haveNext){
            int kn = kk + 16;
            #pragma unroll
            for (int i=0;i<2;i++){
                int gm = rowBase + aM + i*64, gk = kn + aK;
                aR[i] = (gm < M && gk < k1)
                      ? *reinterpret_cast<const float4*>(Ab + (long long)gm*K + gk) : z4;
            }
            if (!TRANSB){
                int gk = kn + bKn, gn = colBase + bNn;
                bR = (gk < k1 && gn < N)
                   ? *reinterpret_cast<const float4*>(Bb + (long long)gk*N + gn) : z4;
            } else {
                int gn = colBase + bNt, gk = kn + bKt;
                bR = (gn < N && gk < k1)
                   ? *reinterpret_cast<const float4*>(Bb + (long long)gn*K + gk) : z4;
            }
        }

        /* ---- MMA on current stage ---- */
        const uint32_t* Ac = As[stage];
        const uint32_t* Bc = Bs[stage];
        #pragma unroll
        for (int kb=0; kb<16; kb+=8){
            uint32_t a[2][4], b[4][2];
            #pragma unroll
            for (int mt=0;mt<2;mt++){
                int r = warpM*32 + mt*16 + grp;
                a[mt][0] = Ac[(r  )*20 + kb + qid];
                a[mt][1] = Ac[(r+8)*20 + kb + qid];
                a[mt][2] = Ac[(r  )*20 + kb + qid + 4];
                a[mt][3] = Ac[(r+8)*20 + kb + qid + 4];
            }
            #pragma unroll
            for (int nt=0;nt<4;nt++){
                int cn = warpN*32 + nt*8 + grp;
                if (!TRANSB){
                    b[nt][0] = Bc[(kb+qid  )*72 + cn];
                    b[nt][1] = Bc[(kb+qid+4)*72 + cn];
                } else {
                    b[nt][0] = Bc[cn*20 + kb + qid];
                    b[nt][1] = Bc[cn*20 + kb + qid + 4];
                }
            }
            #pragma unroll
            for (int mt=0;mt<2;mt++){
                #pragma unroll
                for (int nt=0;nt<4;nt++){
                    asm("mma.sync.aligned.m16n8k8.row.col.f32.tf32.tf32.f32 "
                        "{%0,%1,%2,%3}, {%4,%5,%6,%7}, {%8,%9}, {%0,%1,%2,%3};"
                        : "+f"(c[mt][nt][0]), "+f"(c[mt][nt][1]),
                          "+f"(c[mt][nt][2]), "+f"(c[mt][nt][3])
                        : "r"(a[mt][0]), "r"(a[mt][1]), "r"(a[mt][2]), "r"(a[mt][3]),
                          "r"(b[nt][0]), "r"(b[nt][1]));
                }
            }
        }

        if (haveNext){
            int st = stage ^ 1;
            #pragma unroll
            for (int i=0;i<2;i++){
                uint4 u = make_uint4(f2tf32(aR[i].x), f2tf32(aR[i].y),
                                     f2tf32(aR[i].z), f2tf32(aR[i].w));
                *reinterpret_cast<uint4*>(&As[st][(aM + i*64)*20 + aK]) = u;
            }
            uint4 u = make_uint4(f2tf32(bR.x), f2tf32(bR.y),
                                 f2tf32(bR.z), f2tf32(bR.w));
            if (!TRANSB) *reinterpret_cast<uint4*>(&Bs[st][bKn*72 + bNn]) = u;
            else         *reinterpret_cast<uint4*>(&Bs[st][bNt*20 + bKt]) = u;
            __syncthreads();
            stage = st;
        }
    }

    /* ---- epilogue ---- */
    #pragma unroll
    for (int mt=0;mt<2;mt++){
        #pragma unroll
        for (int nt=0;nt<4;nt++){
            int row0 = rowBase + warpM*32 + mt*16 + grp;
            int col0 = colBase + warpN*32 + nt*8 + qid*2;
            #pragma unroll
            for (int r=0;r<4;r++){
                int row = row0 + (r>>1)*8;
                int col = col0 + (r&1);
                if (row < M && col < N){
                    float v = c[mt][nt][r];
                    if (bias) v += bias[col];
                    if (act == 1) v = fmaxf(v, 0.f);
                    if (Res) v += Res[(long long)row*N + col];
                    Cb[(long long)row*N + col] = v;
                }
            }
        }
    }
}

/* --------------------------- fp32 GEMM (small) ---------------------------- */
__global__ void gemm_k(const float* __restrict__ A, const float* __restrict__ B,
                       const float* __restrict__ bias, const float* __restrict__ Res,
                       float* __restrict__ C,
                       int M, int N, int K,
                       long long sA, long long sB, long long sC,
                       int transB, int act, int kChunk)
{
    const int bz = blockIdx.z;
    const float* Ab = A + (long long)bz * sA;
    const float* Bb = B + (long long)bz * sB;
    float* Cb = C + (long long)bz * sC;
    int k0 = 0, k1 = K;
    if (kChunk > 0){ k0 = bz*kChunk; k1 = min(K, k0 + kChunk); }

    __shared__ float Ast[16][68];
    __shared__ float Bs [16][68];

    const int tid = threadIdx.x;
    const int tx = tid & 15, ty = tid >> 4;
    const int rowBase = blockIdx.y * 64;
    const int colBase = blockIdx.x * 64;

    float acc[4][4];
    #pragma unroll
    for (int i=0;i<4;i++){
        #pragma unroll
        for (int j=0;j<4;j++) acc[i][j]=0.f;
    }

    for (int kk = k0; kk < k1; kk += 16){
        #pragma unroll
        for (int i=0;i<4;i++){
            int idx = tid + i*256;
            int m = idx >> 4, kq = idx & 15;
            int gm = rowBase + m, gk = kk + kq;
            float v = 0.f;
            if (gm < M && gk < k1) v = Ab[(long long)gm*K + gk];
            Ast[kq][m] = v;
        }
        #pragma unroll
        for (int i=0;i<4;i++){
            int idx = tid + i*256;
            int kq = idx >> 6, n = idx & 63;
            int gk = kk + kq, gn = colBase + n;
            float v = 0.f;
            if (gn < N && gk < k1)
                v = transB ? Bb[(long long)gn*K + gk] : Bb[(long long)gk*N + gn];
            Bs[kq][n] = v;
        }
        __syncthreads();
        #pragma unroll
        for (int kq=0;kq<16;kq++){
            float4 av = *reinterpret_cast<const float4*>(&Ast[kq][ty*4]);
            float4 bv = *reinterpret_cast<const float4*>(&Bs [kq][tx*4]);
            float am[4] = {av.x,av.y,av.z,av.w};
            float bn[4] = {bv.x,bv.y,bv.z,bv.w};
            #pragma unroll
            for (int i=0;i<4;i++){
                #pragma unroll
                for (int j=0;j<4;j++) acc[i][j] += am[i]*bn[j];
            }
        }
        __syncthreads();
    }
    #pragma unroll
    for (int i=0;i<4;i++){
        int gm = rowBase + ty*4 + i;
        if (gm >= M) continue;
        #pragma unroll
        for (int j=0;j<4;j++){
            int gn = colBase + tx*4 + j;
            if (gn >= N) continue;
            float v = acc[i][j];
            if (bias) v += bias[gn];
            if (act == 1) v = fmaxf(v, 0.f);
            if (Res) v += Res[(long long)gm*N + gn];
            Cb[(long long)gm*N + gn] = v;
        }
    }
}

/* ------------------------- elementwise / fused --------------------------- */
__global__ void build_hcat_k(const float* __restrict__ x, const float* __restrict__ W_in,
                             const float* __restrict__ b_in, const float* __restrict__ adp,
                             float* __restrict__ out)
{
    long long idx = (long long)blockIdx.x*blockDim.x + threadIdx.x;
    if (idx >= (long long)MM*DD) return;
    int d = (int)(idx % DD);
    long long tn = idx / DD;          /* t*NN + n (t-major) */
    int n = (int)(tn % NN);
    int t = (int)(tn / NN);
    float v;
    if (d < 24){
        const float* xr = x + ((long long)n*TT + t)*3;
        v = b_in[d] + xr[0]*W_in[d] + xr[1]*W_in[24+d] + xr[2]*W_in[48+d];
    } else {
        v = adp[tn*80 + (d-24)];
    }
    out[idx] = v;
}

__global__ void softmax_k(float* __restrict__ g)
{
    long long row = (long long)blockIdx.x*4 + (threadIdx.x>>5);
    if (row >= MM) return;
    int lane = threadIdx.x & 31;
    float* p = g + row*NN;
    float r[13];
    float mx = -3.4e38f;
    #pragma unroll
    for (int i=0;i<13;i++){ int j=lane+i*32; r[i] = (j<NN)? p[j] : -3.4e38f; mx = fmaxf(mx, r[i]); }
    #pragma unroll
    for (int o=16;o;o>>=1) mx = fmaxf(mx, __shfl_xor_sync(0xffffffffu, mx, o));
    float s = 0.f;
    #pragma unroll
    for (int i=0;i<13;i++){ int j=lane+i*32; if (j<NN){ r[i]=expf(r[i]-mx); s+=r[i]; } }
    #pragma unroll
    for (int o=16;o;o>>=1) s += __shfl_xor_sync(0xffffffffu, s, o);
    float inv = 1.f/s;
    #pragma unroll
    for (int i=0;i<13;i++){ int j=lane+i*32; if (j<NN) p[j] = r[i]*inv; }
}

/* kvs[b,h,m,d] = sum_l kn[l,m]*v[l,d] ; ksum[b,h,m] = sum_l kn[l,m] */
__global__ void attn_kvs_k(const float* __restrict__ qkv, float* __restrict__ kvs,
                           float* __restrict__ ksum, int L, int spatial)
{
    int b = blockIdx.x, h = blockIdx.y;
    __shared__ float sk[32][27];
    __shared__ float sv[32][27];
    __shared__ float ss[32];
    int tid = threadIdx.x;
    int mi[3], di[3]; bool ok[3];
    #pragma unroll
    for (int i=0;i<3;i++){ int p=tid+i*256; ok[i]=(p<676); mi[i]=p/26; di[i]=p-26*(p/26); }
    float acc[3] = {0.f,0.f,0.f};
    float asum = 0.f;
    for (int l0=0; l0<L; l0+=32){
        int lc = min(32, L-l0);
        for (int idx=tid; idx<lc*26; idx+=256){
            int r = idx/26, c = idx-r*26;
            int l = l0 + r;
            long long base = spatial ? ((long long)b*NN + l)*QKVW : ((long long)l*NN + b)*QKVW;
            sk[r][c] = qkv[base + DD   + h*HD + c];
            sv[r][c] = qkv[base + 2*DD + h*HD + c];
        }
        __syncthreads();
        if (tid < lc){
            float s=0.f;
            #pragma unroll
            for (int c=0;c<26;c++){ float k=sk[tid][c]; s += k*k; }
            ss[tid] = 1.f/fmaxf(sqrtf(s), 1e-12f);
        }
        __syncthreads();
        for (int idx=tid; idx<lc*26; idx+=256){
            int r = idx/26, c = idx-r*26;
            sk[r][c] *= ss[r];
        }
        __syncthreads();
        for (int l=0;l<lc;l++){
            #pragma unroll
            for (int i=0;i<3;i++)
                if (ok[i]) acc[i] += sk[l][mi[i]]*sv[l][di[i]];
        }
        if (tid < 26){
            for (int l=0;l<lc;l++) asum += sk[l][tid];
        }
        __syncthreads();
    }
    long long ob = ((long long)b*HH + h);
    #pragma unroll
    for (int i=0;i<3;i++){ int p=tid+i*256; if (p<676) kvs[ob*676 + p] = acc[i]; }
    if (tid<26) ksum[ob*26 + tid] = asum;
}

/* out = (qn@kvs + L*v) / (qn.ksum + L) ; one warp per (b,h,l) */
__global__ void attn_out_k(const float* __restrict__ qkv, const float* __restrict__ kvs,
                           const float* __restrict__ ksum, float* __restrict__ cat,
                           int L, int spatial)
{
    int b = blockIdx.x, h = blockIdx.y;
    int warp = threadIdx.x >> 5, lane = threadIdx.x & 31;
    __shared__ float skv[676];
    __shared__ float sks[26];
    long long ob = ((long long)b*HH + h);
    for (int idx=threadIdx.x; idx<676; idx+=128) skv[idx] = kvs[ob*676+idx];
    if (threadIdx.x < 26) sks[threadIdx.x] = ksum[ob*26+threadIdx.x];
    __syncthreads();
    int l = blockIdx.z*4 + warp;
    if (l >= L) return;
    long long base = spatial ? ((long long)b*NN + l)*QKVW : ((long long)l*NN + b)*QKVW;
    float q = (lane < 26) ? qkv[base + h*HD + lane] : 0.f;
    float sq = q*q;
    #pragma unroll
    for (int o=16;o;o>>=1) sq += __shfl_xor_sync(0xffffffffu, sq, o);
    float qn = q * (1.f/fmaxf(sqrtf(sq), 1e-12f));
    float dp = (lane<26) ? qn*sks[lane] : 0.f;
    #pragma unroll
    for (int o=16;o;o>>=1) dp += __shfl_xor_sync(0xffffffffu, dp, o);
    float den = dp + (float)L;
    float num = 0.f;
    #pragma unroll
    for (int m=0;m<26;m++){
        float qm = __shfl_sync(0xffffffffu, qn, m);
        if (lane < 26) num += qm * skv[m*26 + lane];
    }
    if (lane < 26){
        float v = qkv[base + 2*DD + h*HD + lane];
        float o = (num + (float)L * v)/den;
        long long cb = spatial ? ((long long)b*NN + l)*CATW + h*HD
                               : ((long long)l*NN + b)*CATW + DD + h*HD;
        cat[cb + lane] = o;
    }
}

/* h1 = LN(2*(h + a0*pw0 + 0.01*a1*pw1)) */
__global__ void combine_ln1_k(const float* __restrict__ h, const float* __restrict__ a0,
                              const float* __restrict__ pw0, const float* __restrict__ a1,
                              const float* __restrict__ pw1, const float* __restrict__ gam,
                              const float* __restrict__ bet, float* __restrict__ out)
{
    long long row = (long long)blockIdx.x*4 + (threadIdx.x>>5);
    if (row >= MM) return;
    int lane = threadIdx.x & 31;
    long long base = row*DD;
    float v[4]; float s = 0.f;
    #pragma unroll
    for (int i=0;i<4;i++){
        int j = lane + i*32;
        if (j < DD){
            float x = 2.f*(h[base+j] + a0[base+j]*pw0[base+j] + 0.01f*a1[base+j]*pw1[base+j]);
            v[i]=x; s+=x;
        } else v[i]=0.f;
    }
    #pragma unroll
    for (int o=16;o;o>>=1) s += __shfl_xor_sync(0xffffffffu, s, o);
    float mean = s * (1.f/DD);
    float vs = 0.f;
    #pragma unroll
    for (int i=0;i<4;i++){ int j=lane+i*32; if (j<DD){ float d=v[i]-mean; vs += d*d; } }
    #pragma unroll
    for (int o=16;o;o>>=1) vs += __shfl_xor_sync(0xffffffffu, vs, o);
    float inv = rsqrtf(vs*(1.f/DD) + 1e-5f);
    #pragma unroll
    for (int i=0;i<4;i++){ int j=lane+i*32; if (j<DD) out[base+j] = (v[i]-mean)*inv*gam[j] + bet[j]; }
}

__global__ void ln_k(const float* __restrict__ in, const float* __restrict__ gam,
                     const float* __restrict__ bet, float* __restrict__ out)
{
    long long row = (long long)blockIdx.x*4 + (threadIdx.x>>5);
    if (row >= MM) return;
    int lane = threadIdx.x & 31;
    const float* p = in + row*DD;
    float v[4]; float s = 0.f;
    #pragma unroll
    for (int i=0;i<4;i++){ int j=lane+i*32; v[i] = (j<DD)? p[j] : 0.f; s += v[i]; }
    #pragma unroll
    for (int o=16;o;o>>=1) s += __shfl_xor_sync(0xffffffffu, s, o);
    float mean = s * (1.f/DD);
    float vs = 0.f;
    #pragma unroll
    for (int i=0;i<4;i++){ int j=lane+i*32; if (j<DD){ float d=v[i]-mean; vs += d*d; } }
    #pragma unroll
    for (int o=16;o;o>>=1) vs += __shfl_xor_sync(0xffffffffu, vs, o);
    float inv = rsqrtf(vs*(1.f/DD) + 1e-5f);
    float* q = out + row*DD;
    #pragma unroll
    for (int i=0;i<4;i++){ int j=lane+i*32; if (j<DD) q[j] = (v[i]-mean)*inv*gam[j] + bet[j]; }
}

/* h2 [T,N,D] -> h2T [N, T*D] */
__global__ void transpose_k(const float* __restrict__ in, float* __restrict__ out)
{
    long long idx = (long long)blockIdx.x*blockDim.x + threadIdx.x;
    if (idx >= (long long)MM*DD) return;
    int d = (int)(idx % DD);
    long long tn = idx / DD;
    int n = (int)(tn % NN);
    int t = (int)(tn / NN);
    out[(long long)n*(TT*DD) + (long long)t*DD + d] = in[idx];
}

__global__ void ep_reduce_k(const float* __restrict__ part, const float* __restrict__ ep_b,
                            float* __restrict__ y)
{
    int idx = blockIdx.x*blockDim.x + threadIdx.x;
    if (idx >= NN*DD) return;
    float s = ep_b[idx % DD];
    #pragma unroll
    for (int j=0;j<EPK_SPLIT;j++) s += part[(long long)j*(NN*DD) + idx];
    y[idx] = s;
}

/* ------------------------------ host side -------------------------------- */
static void gemm(const float*A,const float*B,const float*bias,const float*Res,float*C,
                 int M,int N,int K,long long sA,long long sB,long long sC,
                 int transB,int act,int kChunk,int batch)
{
    dim3 grid((N+63)/64, (M+63)/64, batch);
    gemm_k<<<grid, 256>>>(A,B,bias,Res,C,M,N,K,sA,sB,sC,transB,act,kChunk);
}

static void gemm_tf(const float*A,const float*B,const float*bias,const float*Res,float*C,
                    int M,int N,int K,long long sA,long long sB,long long sC,
                    int transB,int act,int kChunk,int batch)
{
    dim3 grid((N+63)/64, (M+127)/128, batch);
    if (transB) gemm_tf32_k<1><<<grid, 256>>>(A,B,bias,Res,C,M,N,K,sA,sB,sC,act,kChunk);
    else        gemm_tf32_k<0><<<grid, 256>>>(A,B,bias,Res,C,M,N,K,sA,sB,sC,act,kChunk);
}

extern "C" void kernel_launch(void* const* d_in, const int* in_sizes, int n_in,
                              void* d_out, int out_size)
{
    const float* x     = (const float*)d_in[0];
    const float* W_in  = (const float*)d_in[1];
    const float* b_in  = (const float*)d_in[2];
    const float* adp   = (const float*)d_in[3];
    const float* W_tp  = (const float*)d_in[4];
    const float* b_tp  = (const float*)d_in[5];
    const float* qkv_w = (const float*)d_in[6];
    const float* op_w  = (const float*)d_in[7];
    const float* op_b  = (const float*)d_in[8];
    const float* pw_w  = (const float*)d_in[9];
    const float* pw_b  = (const float*)d_in[10];
    const float* fc_w1 = (const float*)d_in[11];
    const float* fc_b1 = (const float*)d_in[12];
    const float* fc_w2 = (const float*)d_in[13];
    const float* fc_b2 = (const float*)d_in[14];
    const float* ln1_g = (const float*)d_in[15];
    const float* ln1_b = (const float*)d_in[16];
    const float* ln2_g = (const float*)d_in[17];
    const float* ln2_b = (const float*)d_in[18];
    const float* ep_w  = (const float*)d_in[19];
    const float* ep_b  = (const float*)d_in[20];
    const float* enc_w1= (const float*)d_in[21];
    const float* enc_b1= (const float*)d_in[22];
    const float* enc_w2= (const float*)d_in[23];
    const float* enc_b2= (const float*)d_in[24];
    const float* out_w = (const float*)d_in[25];
    const float* out_b = (const float*)d_in[26];
    float* out = (float*)d_out;

    float *hcat,*h,*graph,*z1,*qkv,*kvs,*ksum,*cat,*att0,*att1,*pw0,*pw1,*h1,*mid,*tmp,*h2,*h2T,*part,*y,*ymid;
    cudaGetSymbolAddress((void**)&hcat, g_hcat);
    cudaGetSymbolAddress((void**)&h,    g_h);
    cudaGetSymbolAddress((void**)&graph,g_graph);
    cudaGetSymbolAddress((void**)&z1,   g_z1);
    cudaGetSymbolAddress((void**)&qkv,  g_qkv);
    cudaGetSymbolAddress((void**)&kvs,  g_kvs);
    cudaGetSymbolAddress((void**)&ksum, g_ksum);
    cudaGetSymbolAddress((void**)&cat,  g_cat);
    cudaGetSymbolAddress((void**)&att0, g_att0);
    cudaGetSymbolAddress((void**)&att1, g_att1);
    cudaGetSymbolAddress((void**)&pw0,  g_pw0);
    cudaGetSymbolAddress((void**)&pw1,  g_pw1);
    cudaGetSymbolAddress((void**)&h1,   g_h1);
    cudaGetSymbolAddress((void**)&mid,  g_mid);
    cudaGetSymbolAddress((void**)&tmp,  g_tmp);
    cudaGetSymbolAddress((void**)&h2,   g_h2);
    cudaGetSymbolAddress((void**)&h2T,  g_h2T);
    cudaGetSymbolAddress((void**)&part, g_part);
    cudaGetSymbolAddress((void**)&y,    g_y);
    cudaGetSymbolAddress((void**)&ymid, g_ymid);

    const long long tot = (long long)MM*DD;

    /* 1. hcat = [x@W_in + b_in, adp]  -> [T,N,104] */
    build_hcat_k<<<(unsigned)((tot+255)/256), 256>>>(x, W_in, b_in, adp, hcat);

    /* 2. h = hcat @ W_tp + b_tp */
    gemm_tf(hcat, W_tp, b_tp, nullptr, h, MM, DD, DD, 0,0,0, 0,0,0, 1);

    /* 3. graph = relu(adp_t @ adp_t^T), batched over t */
    gemm_tf(adp, adp, nullptr, nullptr, graph, NN, NN, 80,
            (long long)NN*80, (long long)NN*80, (long long)NN*NN, 1, 1, 0, TT);

    /* 4. softmax rows */
    softmax_k<<<(MM+3)/4, 128>>>(graph);

    /* 5. z1 = graph @ h_t, batched over t */
    gemm_tf(graph, h, nullptr, nullptr, z1, NN, DD, NN,
            (long long)NN*NN, (long long)NN*DD, (long long)NN*DD, 0, 0, 0, TT);

    /* 6. att0 = fast_attn(h, weights[0]) */
    gemm_tf(h, qkv_w, nullptr, nullptr, qkv, MM, QKVW, DD, 0,0,0, 0,0,0, 1);
    attn_kvs_k<<<dim3(TT,HH), 256>>>(qkv, kvs, ksum, NN, 1);
    attn_out_k<<<dim3(TT,HH,(NN+3)/4), 128>>>(qkv, kvs, ksum, cat, NN, 1);
    attn_kvs_k<<<dim3(NN,HH), 256>>>(qkv, kvs, ksum, TT, 0);
    attn_out_k<<<dim3(NN,HH,(TT+3)/4), 128>>>(qkv, kvs, ksum, cat, TT, 0);
    gemm_tf(cat, op_w, op_b, nullptr, att0, MM, DD, CATW, 0,0,0, 0,0,0, 1);

    /* 7. att1 = fast_attn(z1, weights[1]) */
    gemm_tf(z1, qkv_w + DD*QKVW, nullptr, nullptr, qkv, MM, QKVW, DD, 0,0,0, 0,0,0, 1);
    attn_kvs_k<<<dim3(TT,HH), 256>>>(qkv, kvs, ksum, NN, 1);
    attn_out_k<<<dim3(TT,HH,(NN+3)/4), 128>>>(qkv, kvs, ksum, cat, NN, 1);
    attn_kvs_k<<<dim3(NN,HH), 256>>>(qkv, kvs, ksum, TT, 0);
    attn_out_k<<<dim3(NN,HH,(TT+3)/4), 128>>>(qkv, kvs, ksum, cat, TT, 0);
    gemm_tf(cat, op_w + CATW*DD, op_b + DD, nullptr, att1, MM, DD, CATW, 0,0,0, 0,0,0, 1);

    /* 8. pw projections */
    gemm_tf(h,    pw_w,         pw_b,      nullptr, pw0, MM, DD, DD, 0,0,0, 0,0,0, 1);
    gemm_tf(att0, pw_w + DD*DD, pw_b + DD, nullptr, pw1, MM, DD, DD, 0,0,0, 0,0,0, 1);

    /* 9. h1 = LN(2*(h + att0*pw0 + 0.01*att1*pw1)) */
    combine_ln1_k<<<(MM+3)/4, 128>>>(h, att0, pw0, att1, pw1, ln1_g, ln1_b, h1);

    /* 10. h2 = LN(h1 + MLP(h1)) */
    gemm_tf(h1,  fc_w1, fc_b1, nullptr, mid, MM, CATW, DD,  0,0,0, 0,1,0, 1);
    gemm_tf(mid, fc_w2, fc_b2, h1,      tmp, MM, DD, CATW,  0,0,0, 0,0,0, 1);
    ln_k<<<(MM+3)/4, 128>>>(tmp, ln2_g, ln2_b, h2);

    /* 11. encoder_proj: y = reshape(h2) @ ep_w + ep_b  (split-K, deterministic) */
    transpose_k<<<(unsigned)((tot+255)/256), 256>>>(h2, h2T);
    gemm_tf(h2T, ep_w, nullptr, nullptr, part, NN, DD, TT*DD,
            0, 0, (long long)NN*DD, 0, 0, EPK_CHUNK, EPK_SPLIT);
    ep_reduce_k<<<(NN*DD+255)/256, 256>>>(part, ep_b, y);

    /* 12. three residual MLP blocks (small; fp32) */
    for (int i=0;i<3;i++){
        gemm(y,    enc_w1 + (long long)i*DD*CATW, enc_b1 + i*CATW, nullptr, ymid, NN, CATW, DD, 0,0,0, 0,1,0, 1);
        gemm(ymid, enc_w2 + (long long)i*CATW*DD, enc_b2 + i*DD,   y,       y,    NN, DD, CATW, 0,0,0, 0,0,0, 1);
    }

    /* 13. out = y @ out_w + out_b -> [N,365] == d_out layout */
    gemm(y, out_w, out_b, nullptr, out, NN, TT, DD, 0,0,0, 0,0,0, 1);
}

// round 11
// speedup vs baseline: 1.8170x; 1.1291x over previous
#include <cuda_runtime.h>
#include <math.h>
#include <stdint.h>

#define TT 365
#define NN 400
#define DD 104
#define MM (TT*NN)        /* 146000 */
#define HH 4
#define HD 26
#define QKVW 312
#define CATW 208
#define EPK_CHUNK 1040    /* divisible by 16 */
#define EPK_SPLIT 37      /* 37*1040 >= 37960 */

/* ------------ scratch (device globals; no allocs in kernel_launch) ------- */
__device__ float g_hcat[MM*DD];
__device__ float g_h   [MM*DD];
__device__ float g_graph[TT*NN*NN];
__device__ float g_z1  [MM*DD];
__device__ float g_qkv [MM*QKVW];
__device__ float g_kvs [NN*HH*HD*HD];
__device__ float g_ksum[NN*HH*HD];
__device__ float g_cat [MM*CATW];
__device__ float g_att0[MM*DD];
__device__ float g_att1[MM*DD];
__device__ float g_pw0 [MM*DD];
__device__ float g_pw1 [MM*DD];
__device__ float g_h1  [MM*DD];
__device__ float g_mid [MM*CATW];
__device__ float g_tmp [MM*DD];
__device__ float g_h2  [MM*DD];
__device__ float g_h2T [MM*DD];
__device__ float g_part[EPK_SPLIT*NN*DD];
__device__ float g_y   [NN*DD];
__device__ float g_ymid[NN*CATW];

/* ----------------------- tf32 tensor-core GEMM --------------------------- */
__device__ __forceinline__ uint32_t f2tf32(float v){
    uint32_t u; asm("cvt.rna.tf32.f32 %0, %1;" : "=r"(u) : "f"(v)); return u;
}

/* C[M,N] = act(A[M,K] @ B) + bias (+Res). TRANSB: B is [N,K].
   Batched via blockIdx.z (strides). kChunk>0: blockIdx.z selects K-range.
   Tile 256x64x16, 256 threads, 8 warps (each 32 rows x 64 cols, m16n8k8).
   Double-buffered smem, float4 LDG + STS.128, one sync per k-iter.
   Smem layouts (32-bit words):
     As[m][k] stride 20  -> frag addr (grp*20+qid)%32 hits all 32 banks
     Bs[k][n] stride 72  -> frag addr (qid*8+grp)%32 hits all 32 banks
     Bs[n][k] stride 20 (TRANSB) -> same property as As. */
template<int TRANSB>
__global__ void __launch_bounds__(256,2)
gemm_tf32_k(const float* __restrict__ A, const float* __restrict__ B,
            const float* __restrict__ bias, const float* __restrict__ Res,
            float* __restrict__ C,
            int M, int N, int K,
            long long sA, long long sB, long long sC,
            int act, int kChunk)
{
    const int bz = blockIdx.z;
    const float* Ab = A + (long long)bz * sA;
    const float* Bb = B + (long long)bz * sB;
    float* Cb = C + (long long)bz * sC;
    int k0 = 0, k1 = K;
    if (kChunk > 0){ k0 = bz*kChunk; k1 = min(K, k0 + kChunk); }

    __shared__ uint32_t As[2][5120];   /* 256 rows * stride 20 */
    __shared__ uint32_t Bs[2][1280];   /* 16*72=1152 or 64*20=1280 */

    const int tid  = threadIdx.x;
    const int lane = tid & 31;
    const int warp = tid >> 5;         /* 0..7 -> rows 32*warp */
    const int grp = lane >> 2;         /* 0..7 */
    const int qid = lane & 3;          /* 0..3 */
    const int rowBase = blockIdx.y * 256;
    const int colBase = blockIdx.x * 64;

    /* load-thread mapping */
    const int aM = tid >> 2;           /* 0..63 (+64,+128,+192) */
    const int aK = (tid & 3) * 4;
    const int bKn = tid >> 4;          /* normal: k 0..15 */
    const int bNn = (tid & 15) * 4;    /* normal: n 0,4,..60 */
    const int bNt = tid >> 2;          /* transB: n 0..63 */
    const int bKt = (tid & 3) * 4;     /* transB: k 0,4,8,12 */

    float4 aR[4]; float4 bR;
    const float4 z4 = make_float4(0.f,0.f,0.f,0.f);

    float c[2][8][4];                  /* mt(16rows) x nt(8cols) x 4 */
    #pragma unroll
    for (int i=0;i<2;i++)
        #pragma unroll
        for (int j=0;j<8;j++)
            #pragma unroll
            for (int r=0;r<4;r++) c[i][j][r]=0.f;

    /* ---- prologue: load tile k0 into regs, store to stage 0 ---- */
    {
        int kk = k0;
        #pragma unroll
        for (int i=0;i<4;i++){
            int gm = rowBase + aM + i*64, gk = kk + aK;
            aR[i] = (gm < M && gk < k1)
                  ? *reinterpret_cast<const float4*>(Ab + (long long)gm*K + gk) : z4;
        }
        if (!TRANSB){
            int gk = kk + bKn, gn = colBase + bNn;
            bR = (gk < k1 && gn < N)
               ? *reinterpret_cast<const float4*>(Bb + (long long)gk*N + gn) : z4;
        } else {
            int gn = colBase + bNt, gk = kk + bKt;
            bR = (gn < N && gk < k1)
               ? *reinterpret_cast<const float4*>(Bb + (long long)gn*K + gk) : z4;
        }
        #pragma unroll
        for (int i=0;i<4;i++){
            uint4 u = make_uint4(f2tf32(aR[i].x), f2tf32(aR[i].y),
                                 f2tf32(aR[i].z), f2tf32(aR[i].w));
            *reinterpret_cast<uint4*>(&As[0][(aM + i*64)*20 + aK]) = u;
        }
        {
            uint4 u = make_uint4(f2tf32(bR.x), f2tf32(bR.y),
                                 f2tf32(bR.z), f2tf32(bR.w));
            if (!TRANSB) *reinterpret_cast<uint4*>(&Bs[0][bKn*72 + bNn]) = u;
            else         *reinterpret_cast<uint4*>(&Bs[0][bNt*20 + bKt]) = u;
        }
    }
    __syncthreads();

    int stage = 0;
    for (int kk = k0; kk < k1; kk += 16){
        const bool haveNext = (kk + 16) < k1;
        if (haveNext){
            int kn = kk + 16;
            #pragma unroll
            for (int i=0;i<4;i++){
                int gm = rowBase + aM + i*64, gk = kn + aK;
                aR[i] = (gm < M && gk < k1)
                      ? *reinterpret_cast<const float4*>(Ab + (long long)gm*K + gk) : z4;
            }
            if (!TRANSB){
                int gk = kn + bKn, gn = colBase + bNn;
                bR = (gk < k1 && gn < N)
                   ? *reinterpret_cast<const float4*>(Bb + (long long)gk*N + gn) : z4;
            } else {
                int gn = colBase + bNt, gk = kn + bKt;
                bR = (gn < N && gk < k1)
                   ? *reinterpret_cast<const float4*>(Bb + (long long)gn*K + gk) : z4;
            }
        }

        /* ---- MMA on current stage ---- */
        const uint32_t* Ac = As[stage];
        const uint32_t* Bc = Bs[stage];
        #pragma unroll
        for (int kb=0; kb<16; kb+=8){
            uint32_t a[2][4], b[8][2];
            #pragma unroll
            for (int mt=0;mt<2;mt++){
                int r = warp*32 + mt*16 + grp;
                a[mt][0] = Ac[(r  )*20 + kb + qid];
                a[mt][1] = Ac[(r+8)*20 + kb + qid];
                a[mt][2] = Ac[(r  )*20 + kb + qid + 4];
                a[mt][3] = Ac[(r+8)*20 + kb + qid + 4];
            }
            #pragma unroll
            for (int nt=0;nt<8;nt++){
                int cn = nt*8 + grp;
                if (!TRANSB){
                    b[nt][0] = Bc[(kb+qid  )*72 + cn];
                    b[nt][1] = Bc[(kb+qid+4)*72 + cn];
                } else {
                    b[nt][0] = Bc[cn*20 + kb + qid];
                    b[nt][1] = Bc[cn*20 + kb + qid + 4];
                }
            }
            #pragma unroll
            for (int mt=0;mt<2;mt++){
                #pragma unroll
                for (int nt=0;nt<8;nt++){
                    asm("mma.sync.aligned.m16n8k8.row.col.f32.tf32.tf32.f32 "
                        "{%0,%1,%2,%3}, {%4,%5,%6,%7}, {%8,%9}, {%0,%1,%2,%3};"
                        : "+f"(c[mt][nt][0]), "+f"(c[mt][nt][1]),
                          "+f"(c[mt][nt][2]), "+f"(c[mt][nt][3])
                        : "r"(a[mt][0]), "r"(a[mt][1]), "r"(a[mt][2]), "r"(a[mt][3]),
                          "r"(b[nt][0]), "r"(b[nt][1]));
                }
            }
        }

        if (haveNext){
            int st = stage ^ 1;
            #pragma unroll
            for (int i=0;i<4;i++){
                uint4 u = make_uint4(f2tf32(aR[i].x), f2tf32(aR[i].y),
                                     f2tf32(aR[i].z), f2tf32(aR[i].w));
                *reinterpret_cast<uint4*>(&As[st][(aM + i*64)*20 + aK]) = u;
            }
            uint4 u = make_uint4(f2tf32(bR.x), f2tf32(bR.y),
                                 f2tf32(bR.z), f2tf32(bR.w));
            if (!TRANSB) *reinterpret_cast<uint4*>(&Bs[st][bKn*72 + bNn]) = u;
            else         *reinterpret_cast<uint4*>(&Bs[st][bNt*20 + bKt]) = u;
            __syncthreads();
            stage = st;
        }
    }

    /* ---- epilogue: STG.64 pairs (cols qid*2, qid*2+1) ---- */
    #pragma unroll
    for (int mt=0;mt<2;mt++){
        #pragma unroll
        for (int nt=0;nt<8;nt++){
            int row0 = rowBase + warp*32 + mt*16 + grp;
            int col0 = colBase + nt*8 + qid*2;
            #pragma unroll
            for (int half=0; half<2; half++){
                int row = row0 + half*8;
                if (row >= M) continue;
                float e0 = c[mt][nt][half*2+0];
                float e1 = c[mt][nt][half*2+1];
                if (col0 + 1 < N){
                    if (bias){ e0 += bias[col0]; e1 += bias[col0+1]; }
                    if (act == 1){ e0 = fmaxf(e0,0.f); e1 = fmaxf(e1,0.f); }
                    if (Res){
                        float2 rv = *reinterpret_cast<const float2*>(Res + (long long)row*N + col0);
                        e0 += rv.x; e1 += rv.y;
                    }
                    *reinterpret_cast<float2*>(Cb + (long long)row*N + col0) =
                        make_float2(e0, e1);
                } else if (col0 < N){
                    if (bias) e0 += bias[col0];
                    if (act == 1) e0 = fmaxf(e0,0.f);
                    if (Res) e0 += Res[(long long)row*N + col0];
                    Cb[(long long)row*N + col0] = e0;
                }
            }
        }
    }
}

/* --------------------------- fp32 GEMM (small) ---------------------------- */
__global__ void gemm_k(const float* __restrict__ A, const float* __restrict__ B,
                       const float* __restrict__ bias, const float* __restrict__ Res,
                       float* __restrict__ C,
                       int M, int N, int K,
                       long long sA, long long sB, long long sC,
                       int transB, int act, int kChunk)
{
    const int bz = blockIdx.z;
    const float* Ab = A + (long long)bz * sA;
    const float* Bb = B + (long long)bz * sB;
    float* Cb = C + (long long)bz * sC;
    int k0 = 0, k1 = K;
    if (kChunk > 0){ k0 = bz*kChunk; k1 = min(K, k0 + kChunk); }

    __shared__ float Ast[16][68];
    __shared__ float Bs [16][68];

    const int tid = threadIdx.x;
    const int tx = tid & 15, ty = tid >> 4;
    const int rowBase = blockIdx.y * 64;
    const int colBase = blockIdx.x * 64;

    float acc[4][4];
    #pragma unroll
    for (int i=0;i<4;i++){
        #pragma unroll
        for (int j=0;j<4;j++) acc[i][j]=0.f;
    }

    for (int kk = k0; kk < k1; kk += 16){
        #pragma unroll
        for (int i=0;i<4;i++){
            int idx = tid + i*256;
            int m = idx >> 4, kq = idx & 15;
            int gm = rowBase + m, gk = kk + kq;
            float v = 0.f;
            if (gm < M && gk < k1) v = Ab[(long long)gm*K + gk];
            Ast[kq][m] = v;
        }
        #pragma unroll
        for (int i=0;i<4;i++){
            int idx = tid + i*256;
            int kq = idx >> 6, n = idx & 63;
            int gk = kk + kq, gn = colBase + n;
            float v = 0.f;
            if (gn < N && gk < k1)
                v = transB ? Bb[(long long)gn*K + gk] : Bb[(long long)gk*N + gn];
            Bs[kq][n] = v;
        }
        __syncthreads();
        #pragma unroll
        for (int kq=0;kq<16;kq++){
            float4 av = *reinterpret_cast<const float4*>(&Ast[kq][ty*4]);
            float4 bv = *reinterpret_cast<const float4*>(&Bs [kq][tx*4]);
            float am[4] = {av.x,av.y,av.z,av.w};
            float bn[4] = {bv.x,bv.y,bv.z,bv.w};
            #pragma unroll
            for (int i=0;i<4;i++){
                #pragma unroll
                for (int j=0;j<4;j++) acc[i][j] += am[i]*bn[j];
            }
        }
        __syncthreads();
    }
    #pragma unroll
    for (int i=0;i<4;i++){
        int gm = rowBase + ty*4 + i;
        if (gm >= M) continue;
        #pragma unroll
        for (int j=0;j<4;j++){
            int gn = colBase + tx*4 + j;
            if (gn >= N) continue;
            float v = acc[i][j];
            if (bias) v += bias[gn];
            if (act == 1) v = fmaxf(v, 0.f);
            if (Res) v += Res[(long long)gm*N + gn];
            Cb[(long long)gm*N + gn] = v;
        }
    }
}

/* ------------------------- elementwise / fused --------------------------- */
__global__ void build_hcat_k(const float* __restrict__ x, const float* __restrict__ W_in,
                             const float* __restrict__ b_in, const float* __restrict__ adp,
                             float* __restrict__ out)
{
    long long idx = (long long)blockIdx.x*blockDim.x + threadIdx.x;
    if (idx >= (long long)MM*DD) return;
    int d = (int)(idx % DD);
    long long tn = idx / DD;          /* t*NN + n (t-major) */
    int n = (int)(tn % NN);
    int t = (int)(tn / NN);
    float v;
    if (d < 24){
        const float* xr = x + ((long long)n*TT + t)*3;
        v = b_in[d] + xr[0]*W_in[d] + xr[1]*W_in[24+d] + xr[2]*W_in[48+d];
    } else {
        v = adp[tn*80 + (d-24)];
    }
    out[idx] = v;
}

__global__ void softmax_k(float* __restrict__ g)
{
    long long row = (long long)blockIdx.x*4 + (threadIdx.x>>5);
    if (row >= MM) return;
    int lane = threadIdx.x & 31;
    float* p = g + row*NN;
    float r[13];
    float mx = -3.4e38f;
    #pragma unroll
    for (int i=0;i<13;i++){ int j=lane+i*32; r[i] = (j<NN)? p[j] : -3.4e38f; mx = fmaxf(mx, r[i]); }
    #pragma unroll
    for (int o=16;o;o>>=1) mx = fmaxf(mx, __shfl_xor_sync(0xffffffffu, mx, o));
    float s = 0.f;
    #pragma unroll
    for (int i=0;i<13;i++){ int j=lane+i*32; if (j<NN){ r[i]=expf(r[i]-mx); s+=r[i]; } }
    #pragma unroll
    for (int o=16;o;o>>=1) s += __shfl_xor_sync(0xffffffffu, s, o);
    float inv = 1.f/s;
    #pragma unroll
    for (int i=0;i<13;i++){ int j=lane+i*32; if (j<NN) p[j] = r[i]*inv; }
}

/* kvs[b,h,m,d] = sum_l kn[l,m]*v[l,d] ; ksum[b,h,m] = sum_l kn[l,m] */
__global__ void attn_kvs_k(const float* __restrict__ qkv, float* __restrict__ kvs,
                           float* __restrict__ ksum, int L, int spatial)
{
    int b = blockIdx.x, h = blockIdx.y;
    __shared__ float sk[32][27];
    __shared__ float sv[32][27];
    __shared__ float ss[32];
    int tid = threadIdx.x;
    int mi[3], di[3]; bool ok[3];
    #pragma unroll
    for (int i=0;i<3;i++){ int p=tid+i*256; ok[i]=(p<676); mi[i]=p/26; di[i]=p-26*(p/26); }
    float acc[3] = {0.f,0.f,0.f};
    float asum = 0.f;
    for (int l0=0; l0<L; l0+=32){
        int lc = min(32, L-l0);
        for (int idx=tid; idx<lc*26; idx+=256){
            int r = idx/26, c = idx-r*26;
            int l = l0 + r;
            long long base = spatial ? ((long long)b*NN + l)*QKVW : ((long long)l*NN + b)*QKVW;
            sk[r][c] = qkv[base + DD   + h*HD + c];
            sv[r][c] = qkv[base + 2*DD + h*HD + c];
        }
        __syncthreads();
        if (tid < lc){
            float s=0.f;
            #pragma unroll
            for (int c=0;c<26;c++){ float k=sk[tid][c]; s += k*k; }
            ss[tid] = 1.f/fmaxf(sqrtf(s), 1e-12f);
        }
        __syncthreads();
        for (int idx=tid; idx<lc*26; idx+=256){
            int r = idx/26, c = idx-r*26;
            sk[r][c] *= ss[r];
        }
        __syncthreads();
        for (int l=0;l<lc;l++){
            #pragma unroll
            for (int i=0;i<3;i++)
                if (ok[i]) acc[i] += sk[l][mi[i]]*sv[l][di[i]];
        }
        if (tid < 26){
            for (int l=0;l<lc;l++) asum += sk[l][tid];
        }
        __syncthreads();
    }
    long long ob = ((long long)b*HH + h);
    #pragma unroll
    for (int i=0;i<3;i++){ int p=tid+i*256; if (p<676) kvs[ob*676 + p] = acc[i]; }
    if (tid<26) ksum[ob*26 + tid] = asum;
}

/* out = (qn@kvs + L*v) / (qn.ksum + L) ; one warp per (b,h,l) */
__global__ void attn_out_k(const float* __restrict__ qkv, const float* __restrict__ kvs,
                           const float* __restrict__ ksum, float* __restrict__ cat,
                           int L, int spatial)
{
    int b = blockIdx.x, h = blockIdx.y;
    int warp = threadIdx.x >> 5, lane = threadIdx.x & 31;
    __shared__ float skv[676];
    __shared__ float sks[26];
    long long ob = ((long long)b*HH + h);
    for (int idx=threadIdx.x; idx<676; idx+=128) skv[idx] = kvs[ob*676+idx];
    if (threadIdx.x < 26) sks[threadIdx.x] = ksum[ob*26+threadIdx.x];
    __syncthreads();
    int l = blockIdx.z*4 + warp;
    if (l >= L) return;
    long long base = spatial ? ((long long)b*NN + l)*QKVW : ((long long)l*NN + b)*QKVW;
    float q = (lane < 26) ? qkv[base + h*HD + lane] : 0.f;
    float sq = q*q;
    #pragma unroll
    for (int o=16;o;o>>=1) sq += __shfl_xor_sync(0xffffffffu, sq, o);
    float qn = q * (1.f/fmaxf(sqrtf(sq), 1e-12f));
    float dp = (lane<26) ? qn*sks[lane] : 0.f;
    #pragma unroll
    for (int o=16;o;o>>=1) dp += __shfl_xor_sync(0xffffffffu, dp, o);
    float den = dp + (float)L;
    float num = 0.f;
    #pragma unroll
    for (int m=0;m<26;m++){
        float qm = __shfl_sync(0xffffffffu, qn, m);
        if (lane < 26) num += qm * skv[m*26 + lane];
    }
    if (lane < 26){
        float v = qkv[base + 2*DD + h*HD + lane];
        float o = (num + (float)L * v)/den;
        long long cb = spatial ? ((long long)b*NN + l)*CATW + h*HD
                               : ((long long)l*NN + b)*CATW + DD + h*HD;
        cat[cb + lane] = o;
    }
}

/* h1 = LN(2*(h + a0*pw0 + 0.01*a1*pw1)) */
__global__ void combine_ln1_k(const float* __restrict__ h, const float* __restrict__ a0,
                              const float* __restrict__ pw0, const float* __restrict__ a1,
                              const float* __restrict__ pw1, const float* __restrict__ gam,
                              const float* __restrict__ bet, float* __restrict__ out)
{
    long long row = (long long)blockIdx.x*4 + (threadIdx.x>>5);
    if (row >= MM) return;
    int lane = threadIdx.x & 31;
    long long base = row*DD;
    float v[4]; float s = 0.f;
    #pragma unroll
    for (int i=0;i<4;i++){
        int j = lane + i*32;
        if (j < DD){
            float x = 2.f*(h[base+j] + a0[base+j]*pw0[base+j] + 0.01f*a1[base+j]*pw1[base+j]);
            v[i]=x; s+=x;
        } else v[i]=0.f;
    }
    #pragma unroll
    for (int o=16;o;o>>=1) s += __shfl_xor_sync(0xffffffffu, s, o);
    float mean = s * (1.f/DD);
    float vs = 0.f;
    #pragma unroll
    for (int i=0;i<4;i++){ int j=lane+i*32; if (j<DD){ float d=v[i]-mean; vs += d*d; } }
    #pragma unroll
    for (int o=16;o;o>>=1) vs += __shfl_xor_sync(0xffffffffu, vs, o);
    float inv = rsqrtf(vs*(1.f/DD) + 1e-5f);
    #pragma unroll
    for (int i=0;i<4;i++){ int j=lane+i*32; if (j<DD) out[base+j] = (v[i]-mean)*inv*gam[j] + bet[j]; }
}

__global__ void ln_k(const float* __restrict__ in, const float* __restrict__ gam,
                     const float* __restrict__ bet, float* __restrict__ out)
{
    long long row = (long long)blockIdx.x*4 + (threadIdx.x>>5);
    if (row >= MM) return;
    int lane = threadIdx.x & 31;
    const float* p = in + row*DD;
    float v[4]; float s = 0.f;
    #pragma unroll
    for (int i=0;i<4;i++){ int j=lane+i*32; v[i] = (j<DD)? p[j] : 0.f; s += v[i]; }
    #pragma unroll
    for (int o=16;o;o>>=1) s += __shfl_xor_sync(0xffffffffu, s, o);
    float mean = s * (1.f/DD);
    float vs = 0.f;
    #pragma unroll
    for (int i=0;i<4;i++){ int j=lane+i*32; if (j<DD){ float d=v[i]-mean; vs += d*d; } }
    #pragma unroll
    for (int o=16;o;o>>=1) vs += __shfl_xor_sync(0xffffffffu, vs, o);
    float inv = rsqrtf(vs*(1.f/DD) + 1e-5f);
    float* q = out + row*DD;
    #pragma unroll
    for (int i=0;i<4;i++){ int j=lane+i*32; if (j<DD) q[j] = (v[i]-mean)*inv*gam[j] + bet[j]; }
}

/* h2 [T,N,D] -> h2T [N, T*D] */
__global__ void transpose_k(const float* __restrict__ in, float* __restrict__ out)
{
    long long idx = (long long)blockIdx.x*blockDim.x + threadIdx.x;
    if (idx >= (long long)MM*DD) return;
    int d = (int)(idx % DD);
    long long tn = idx / DD;
    int n = (int)(tn % NN);
    int t = (int)(tn / NN);
    out[(long long)n*(TT*DD) + (long long)t*DD + d] = in[idx];
}

__global__ void ep_reduce_k(const float* __restrict__ part, const float* __restrict__ ep_b,
                            float* __restrict__ y)
{
    int idx = blockIdx.x*blockDim.x + threadIdx.x;
    if (idx >= NN*DD) return;
    float s = ep_b[idx % DD];
    #pragma unroll
    for (int j=0;j<EPK_SPLIT;j++) s += part[(long long)j*(NN*DD) + idx];
    y[idx] = s;
}

/* ------------------------------ host side -------------------------------- */
static void gemm(const float*A,const float*B,const float*bias,const float*Res,float*C,
                 int M,int N,int K,long long sA,long long sB,long long sC,
                 int transB,int act,int kChunk,int batch)
{
    dim3 grid((N+63)/64, (M+63)/64, batch);
    gemm_k<<<grid, 256>>>(A,B,bias,Res,C,M,N,K,sA,sB,sC,transB,act,kChunk);
}

static void gemm_tf(const float*A,const float*B,const float*bias,const float*Res,float*C,
                    int M,int N,int K,long long sA,long long sB,long long sC,
                    int transB,int act,int kChunk,int batch)
{
    dim3 grid((N+63)/64, (M+255)/256, batch);
    if (transB) gemm_tf32_k<1><<<grid, 256>>>(A,B,bias,Res,C,M,N,K,sA,sB,sC,act,kChunk);
    else        gemm_tf32_k<0><<<grid, 256>>>(A,B,bias,Res,C,M,N,K,sA,sB,sC,act,kChunk);
}

extern "C" void kernel_launch(void* const* d_in, const int* in_sizes, int n_in,
                              void* d_out, int out_size)
{
    const float* x     = (const float*)d_in[0];
    const float* W_in  = (const float*)d_in[1];
    const float* b_in  = (const float*)d_in[2];
    const float* adp   = (const float*)d_in[3];
    const float* W_tp  = (const float*)d_in[4];
    const float* b_tp  = (const float*)d_in[5];
    const float* qkv_w = (const float*)d_in[6];
    const float* op_w  = (const float*)d_in[7];
    const float* op_b  = (const float*)d_in[8];
    const float* pw_w  = (const float*)d_in[9];
    const float* pw_b  = (const float*)d_in[10];
    const float* fc_w1 = (const float*)d_in[11];
    const float* fc_b1 = (const float*)d_in[12];
    const float* fc_w2 = (const float*)d_in[13];
    const float* fc_b2 = (const float*)d_in[14];
    const float* ln1_g = (const float*)d_in[15];
    const float* ln1_b = (const float*)d_in[16];
    const float* ln2_g = (const float*)d_in[17];
    const float* ln2_b = (const float*)d_in[18];
    const float* ep_w  = (const float*)d_in[19];
    const float* ep_b  = (const float*)d_in[20];
    const float* enc_w1= (const float*)d_in[21];
    const float* enc_b1= (const float*)d_in[22];
    const float* enc_w2= (const float*)d_in[23];
    const float* enc_b2= (const float*)d_in[24];
    const float* out_w = (const float*)d_in[25];
    const float* out_b = (const float*)d_in[26];
    float* out = (float*)d_out;

    float *hcat,*h,*graph,*z1,*qkv,*kvs,*ksum,*cat,*att0,*att1,*pw0,*pw1,*h1,*mid,*tmp,*h2,*h2T,*part,*y,*ymid;
    cudaGetSymbolAddress((void**)&hcat, g_hcat);
    cudaGetSymbolAddress((void**)&h,    g_h);
    cudaGetSymbolAddress((void**)&graph,g_graph);
    cudaGetSymbolAddress((void**)&z1,   g_z1);
    cudaGetSymbolAddress((void**)&qkv,  g_qkv);
    cudaGetSymbolAddress((void**)&kvs,  g_kvs);
    cudaGetSymbolAddress((void**)&ksum, g_ksum);
    cudaGetSymbolAddress((void**)&cat,  g_cat);
    cudaGetSymbolAddress((void**)&att0, g_att0);
    cudaGetSymbolAddress((void**)&att1, g_att1);
    cudaGetSymbolAddress((void**)&pw0,  g_pw0);
    cudaGetSymbolAddress((void**)&pw1,  g_pw1);
    cudaGetSymbolAddress((void**)&h1,   g_h1);
    cudaGetSymbolAddress((void**)&mid,  g_mid);
    cudaGetSymbolAddress((void**)&tmp,  g_tmp);
    cudaGetSymbolAddress((void**)&h2,   g_h2);
    cudaGetSymbolAddress((void**)&h2T,  g_h2T);
    cudaGetSymbolAddress((void**)&part, g_part);
    cudaGetSymbolAddress((void**)&y,    g_y);
    cudaGetSymbolAddress((void**)&ymid, g_ymid);

    const long long tot = (long long)MM*DD;

    /* 1. hcat = [x@W_in + b_in, adp]  -> [T,N,104] */
    build_hcat_k<<<(unsigned)((tot+255)/256), 256>>>(x, W_in, b_in, adp, hcat);

    /* 2. h = hcat @ W_tp + b_tp */
    gemm_tf(hcat, W_tp, b_tp, nullptr, h, MM, DD, DD, 0,0,0, 0,0,0, 1);

    /* 3. graph = relu(adp_t @ adp_t^T), batched over t */
    gemm_tf(adp, adp, nullptr, nullptr, graph, NN, NN, 80,
            (long long)NN*80, (long long)NN*80, (long long)NN*NN, 1, 1, 0, TT);

    /* 4. softmax rows */
    softmax_k<<<(MM+3)/4, 128>>>(graph);

    /* 5. z1 = graph @ h_t, batched over t */
    gemm_tf(graph, h, nullptr, nullptr, z1, NN, DD, NN,
            (long long)NN*NN, (long long)NN*DD, (long long)NN*DD, 0, 0, 0, TT);

    /* 6. att0 = fast_attn(h, weights[0]) */
    gemm_tf(h, qkv_w, nullptr, nullptr, qkv, MM, QKVW, DD, 0,0,0, 0,0,0, 1);
    attn_kvs_k<<<dim3(TT,HH), 256>>>(qkv, kvs, ksum, NN, 1);
    attn_out_k<<<dim3(TT,HH,(NN+3)/4), 128>>>(qkv, kvs, ksum, cat, NN, 1);
    attn_kvs_k<<<dim3(NN,HH), 256>>>(qkv, kvs, ksum, TT, 0);
    attn_out_k<<<dim3(NN,HH,(TT+3)/4), 128>>>(qkv, kvs, ksum, cat, TT, 0);
    gemm_tf(cat, op_w, op_b, nullptr, att0, MM, DD, CATW, 0,0,0, 0,0,0, 1);

    /* 7. att1 = fast_attn(z1, weights[1]) */
    gemm_tf(z1, qkv_w + DD*QKVW, nullptr, nullptr, qkv, MM, QKVW, DD, 0,0,0, 0,0,0, 1);
    attn_kvs_k<<<dim3(TT,HH), 256>>>(qkv, kvs, ksum, NN, 1);
    attn_out_k<<<dim3(TT,HH,(NN+3)/4), 128>>>(qkv, kvs, ksum, cat, NN, 1);
    attn_kvs_k<<<dim3(NN,HH), 256>>>(qkv, kvs, ksum, TT, 0);
    attn_out_k<<<dim3(NN,HH,(TT+3)/4), 128>>>(qkv, kvs, ksum, cat, TT, 0);
    gemm_tf(cat, op_w + CATW*DD, op_b + DD, nullptr, att1, MM, DD, CATW, 0,0,0, 0,0,0, 1);

    /* 8. pw projections */
    gemm_tf(h,    pw_w,         pw_b,      nullptr, pw0, MM, DD, DD, 0,0,0, 0,0,0, 1);
    gemm_tf(att0, pw_w + DD*DD, pw_b + DD, nullptr, pw1, MM, DD, DD, 0,0,0, 0,0,0, 1);

    /* 9. h1 = LN(2*(h + att0*pw0 + 0.01*att1*pw1)) */
    combine_ln1_k<<<(MM+3)/4, 128>>>(h, att0, pw0, att1, pw1, ln1_g, ln1_b, h1);

    /* 10. h2 = LN(h1 + MLP(h1)) */
    gemm_tf(h1,  fc_w1, fc_b1, nullptr, mid, MM, CATW, DD,  0,0,0, 0,1,0, 1);
    gemm_tf(mid, fc_w2, fc_b2, h1,      tmp, MM, DD, CATW,  0,0,0, 0,0,0, 1);
    ln_k<<<(MM+3)/4, 128>>>(tmp, ln2_g, ln2_b, h2);

    /* 11. encoder_proj: y = reshape(h2) @ ep_w + ep_b  (split-K, deterministic) */
    transpose_k<<<(unsigned)((tot+255)/256), 256>>>(h2, h2T);
    gemm_tf(h2T, ep_w, nullptr, nullptr, part, NN, DD, TT*DD,
            0, 0, (long long)NN*DD, 0, 0, EPK_CHUNK, EPK_SPLIT);
    ep_reduce_k<<<(NN*DD+255)/256, 256>>>(part, ep_b, y);

    /* 12. three residual MLP blocks (small; fp32) */
    for (int i=0;i<3;i++){
        gemm(y,    enc_w1 + (long long)i*DD*CATW, enc_b1 + i*CATW, nullptr, ymid, NN, CATW, DD, 0,0,0, 0,1,0, 1);
        gemm(ymid, enc_w2 + (long long)i*CATW*DD, enc_b2 + i*DD,   y,       y,    NN, DD, CATW, 0,0,0, 0,0,0, 1);
    }

    /* 13. out = y @ out_w + out_b -> [N,365] == d_out layout */
    gemm(y, out_w, out_b, nullptr, out, NN, TT, DD, 0,0,0, 0,0,0, 1);
}

// round 12
// speedup vs baseline: 1.9253x; 1.0596x over previous
#include <cuda_runtime.h>
#include <cuda_fp16.h>
#include <math.h>
#include <stdint.h>

#define TT 365
#define NN 400
#define DD 104
#define MM (TT*NN)        /* 146000 */
#define HH 4
#define HD 26
#define QKVW 312
#define CATW 208
#define EPK_CHUNK 1040    /* divisible by 16 */
#define EPK_SPLIT 37      /* 37*1040 >= 37960 */

/* ------------ scratch (device globals; no allocs in kernel_launch) ------- */
__device__ float g_hcat[MM*DD];
__device__ float g_h   [MM*DD];
__device__ float g_graph[TT*NN*NN];
__device__ float g_z1  [MM*DD];
__device__ float g_qkv [MM*QKVW];
__device__ float g_kvs [NN*HH*HD*HD];
__device__ float g_ksum[NN*HH*HD];
__device__ float g_cat [MM*CATW];
__device__ float g_att0[MM*DD];
__device__ float g_att1[MM*DD];
__device__ float g_pw0 [MM*DD];
__device__ float g_pw1 [MM*DD];
__device__ float g_h1  [MM*DD];
__device__ float g_mid [MM*CATW];
__device__ float g_tmp [MM*DD];
__device__ float g_h2  [MM*DD];
__device__ float g_h2T [MM*DD];
__device__ float g_part[EPK_SPLIT*NN*DD];
__device__ float g_y   [NN*DD];
__device__ float g_ymid[NN*CATW];

/* ----------------------- fp16 tensor-core GEMM --------------------------- */
__device__ __forceinline__ uint32_t packh2(float a, float b){
    __half2 h = __floats2half2_rn(a, b);
    return *reinterpret_cast<uint32_t*>(&h);
}

/* C[M,N] = act(A[M,K] @ B) + bias (+Res). TRANSB: B is [N,K].
   Batched via blockIdx.z (strides). kChunk>0: blockIdx.z selects K-range.
   Tile 256x64x16, 256 threads, 8 warps (each 32 rows x 64 cols, m16n8k16 f16,
   fp32 accumulate). Double-buffered smem, one sync per k-iter.
   Smem (32-bit words = half2 units), stride 12 words/row:
     frag addr (grp*12 + qid) mod 32 covers all 32 banks (12*{0..7} =
     {0,12,24,4,16,28,8,20}); +4 offset likewise. */
template<int TRANSB>
__global__ void __launch_bounds__(256,2)
gemm_f16_k(const float* __restrict__ A, const float* __restrict__ B,
           const float* __restrict__ bias, const float* __restrict__ Res,
           float* __restrict__ C,
           int M, int N, int K,
           long long sA, long long sB, long long sC,
           int act, int kChunk)
{
    const int bz = blockIdx.z;
    const float* Ab = A + (long long)bz * sA;
    const float* Bb = B + (long long)bz * sB;
    float* Cb = C + (long long)bz * sC;
    int k0 = 0, k1 = K;
    if (kChunk > 0){ k0 = bz*kChunk; k1 = min(K, k0 + kChunk); }

    __shared__ uint32_t As[2][3072];   /* 256 rows * 12 words */
    __shared__ uint32_t Bs[2][768];    /* 64 rows * 12 words  */

    const int tid  = threadIdx.x;
    const int lane = tid & 31;
    const int warp = tid >> 5;         /* 0..7 -> rows 32*warp */
    const int grp = lane >> 2;         /* 0..7 */
    const int qid = lane & 3;          /* 0..3 */
    const int rowBase = blockIdx.y * 256;
    const int colBase = blockIdx.x * 64;

    /* load-thread mapping: A rows aM(+64i), k aK..aK+3 ; B rows bN, k bK4..+3 */
    const int aM = tid >> 2;           /* 0..63 */
    const int aK = (tid & 3) * 4;      /* 0,4,8,12 */
    const int bN = tid >> 2;           /* 0..63 */
    const int bK4 = (tid & 3) * 4;     /* 0,4,8,12 */

    float4 aR[4]; float4 bR;
    const float4 z4 = make_float4(0.f,0.f,0.f,0.f);

    float c[2][8][4];                  /* mt(16rows) x nt(8cols) x 4 */
    #pragma unroll
    for (int i=0;i<2;i++)
        #pragma unroll
        for (int j=0;j<8;j++)
            #pragma unroll
            for (int r=0;r<4;r++) c[i][j][r]=0.f;

    /* ---- tile loaders ---- */
    auto loadTile = [&](int kk){
        #pragma unroll
        for (int i=0;i<4;i++){
            int gm = rowBase + aM + i*64, gk = kk + aK;
            aR[i] = (gm < M && gk < k1)
                  ? *reinterpret_cast<const float4*>(Ab + (long long)gm*K + gk) : z4;
        }
        if (!TRANSB){
            int gn = colBase + bN;
            float t0=0.f,t1=0.f,t2=0.f,t3=0.f;
            if (gn < N){
                int gk = kk + bK4;
                if (gk   < k1) t0 = Bb[(long long)(gk  )*N + gn];
                if (gk+1 < k1) t1 = Bb[(long long)(gk+1)*N + gn];
                if (gk+2 < k1) t2 = Bb[(long long)(gk+2)*N + gn];
                if (gk+3 < k1) t3 = Bb[(long long)(gk+3)*N + gn];
            }
            bR = make_float4(t0,t1,t2,t3);
        } else {
            int gn = colBase + bN, gk = kk + bK4;
            bR = (gn < N && gk < k1)
               ? *reinterpret_cast<const float4*>(Bb + (long long)gn*K + gk) : z4;
        }
    };
    auto storeTile = [&](int st){
        #pragma unroll
        for (int i=0;i<4;i++){
            uint2 u = make_uint2(packh2(aR[i].x, aR[i].y), packh2(aR[i].z, aR[i].w));
            *reinterpret_cast<uint2*>(&As[st][(aM + i*64)*12 + aK/2]) = u;
        }
        {
            uint2 u = make_uint2(packh2(bR.x, bR.y), packh2(bR.z, bR.w));
            *reinterpret_cast<uint2*>(&Bs[st][bN*12 + bK4/2]) = u;
        }
    };

    /* ---- prologue ---- */
    loadTile(k0);
    storeTile(0);
    __syncthreads();

    int stage = 0;
    for (int kk = k0; kk < k1; kk += 16){
        const bool haveNext = (kk + 16) < k1;
        if (haveNext) loadTile(kk + 16);

        /* ---- MMA on current stage (one m16n8k16 set consumes all 16 k) ---- */
        const uint32_t* Ac = As[stage];
        const uint32_t* Bc = Bs[stage];
        uint32_t a[2][4], b[8][2];
        #pragma unroll
        for (int mt=0;mt<2;mt++){
            int r = warp*32 + mt*16 + grp;
            a[mt][0] = Ac[(r  )*12 + qid];
            a[mt][1] = Ac[(r+8)*12 + qid];
            a[mt][2] = Ac[(r  )*12 + 4 + qid];
            a[mt][3] = Ac[(r+8)*12 + 4 + qid];
        }
        #pragma unroll
        for (int nt=0;nt<8;nt++){
            int cn = nt*8 + grp;
            b[nt][0] = Bc[cn*12 + qid];
            b[nt][1] = Bc[cn*12 + 4 + qid];
        }
        #pragma unroll
        for (int mt=0;mt<2;mt++){
            #pragma unroll
            for (int nt=0;nt<8;nt++){
                asm("mma.sync.aligned.m16n8k16.row.col.f32.f16.f16.f32 "
                    "{%0,%1,%2,%3}, {%4,%5,%6,%7}, {%8,%9}, {%0,%1,%2,%3};"
                    : "+f"(c[mt][nt][0]), "+f"(c[mt][nt][1]),
                      "+f"(c[mt][nt][2]), "+f"(c[mt][nt][3])
                    : "r"(a[mt][0]), "r"(a[mt][1]), "r"(a[mt][2]), "r"(a[mt][3]),
                      "r"(b[nt][0]), "r"(b[nt][1]));
            }
        }

        if (haveNext){
            int st = stage ^ 1;
            storeTile(st);
            __syncthreads();
            stage = st;
        }
    }

    /* ---- epilogue: STG.64 pairs (cols qid*2, qid*2+1) ---- */
    #pragma unroll
    for (int mt=0;mt<2;mt++){
        #pragma unroll
        for (int nt=0;nt<8;nt++){
            int row0 = rowBase + warp*32 + mt*16 + grp;
            int col0 = colBase + nt*8 + qid*2;
            #pragma unroll
            for (int half=0; half<2; half++){
                int row = row0 + half*8;
                if (row >= M) continue;
                float e0 = c[mt][nt][half*2+0];
                float e1 = c[mt][nt][half*2+1];
                if (col0 + 1 < N){
                    if (bias){ e0 += bias[col0]; e1 += bias[col0+1]; }
                    if (act == 1){ e0 = fmaxf(e0,0.f); e1 = fmaxf(e1,0.f); }
                    if (Res){
                        float2 rv = *reinterpret_cast<const float2*>(Res + (long long)row*N + col0);
                        e0 += rv.x; e1 += rv.y;
                    }
                    *reinterpret_cast<float2*>(Cb + (long long)row*N + col0) =
                        make_float2(e0, e1);
                } else if (col0 < N){
                    if (bias) e0 += bias[col0];
                    if (act == 1) e0 = fmaxf(e0,0.f);
                    if (Res) e0 += Res[(long long)row*N + col0];
                    Cb[(long long)row*N + col0] = e0;
                }
            }
        }
    }
}

/* --------------------------- fp32 GEMM (small) ---------------------------- */
__global__ void gemm_k(const float* __restrict__ A, const float* __restrict__ B,
                       const float* __restrict__ bias, const float* __restrict__ Res,
                       float* __restrict__ C,
                       int M, int N, int K,
                       long long sA, long long sB, long long sC,
                       int transB, int act, int kChunk)
{
    const int bz = blockIdx.z;
    const float* Ab = A + (long long)bz * sA;
    const float* Bb = B + (long long)bz * sB;
    float* Cb = C + (long long)bz * sC;
    int k0 = 0, k1 = K;
    if (kChunk > 0){ k0 = bz*kChunk; k1 = min(K, k0 + kChunk); }

    __shared__ float Ast[16][68];
    __shared__ float Bs [16][68];

    const int tid = threadIdx.x;
    const int tx = tid & 15, ty = tid >> 4;
    const int rowBase = blockIdx.y * 64;
    const int colBase = blockIdx.x * 64;

    float acc[4][4];
    #pragma unroll
    for (int i=0;i<4;i++){
        #pragma unroll
        for (int j=0;j<4;j++) acc[i][j]=0.f;
    }

    for (int kk = k0; kk < k1; kk += 16){
        #pragma unroll
        for (int i=0;i<4;i++){
            int idx = tid + i*256;
            int m = idx >> 4, kq = idx & 15;
            int gm = rowBase + m, gk = kk + kq;
            float v = 0.f;
            if (gm < M && gk < k1) v = Ab[(long long)gm*K + gk];
            Ast[kq][m] = v;
        }
        #pragma unroll
        for (int i=0;i<4;i++){
            int idx = tid + i*256;
            int kq = idx >> 6, n = idx & 63;
            int gk = kk + kq, gn = colBase + n;
            float v = 0.f;
            if (gn < N && gk < k1)
                v = transB ? Bb[(long long)gn*K + gk] : Bb[(long long)gk*N + gn];
            Bs[kq][n] = v;
        }
        __syncthreads();
        #pragma unroll
        for (int kq=0;kq<16;kq++){
            float4 av = *reinterpret_cast<const float4*>(&Ast[kq][ty*4]);
            float4 bv = *reinterpret_cast<const float4*>(&Bs [kq][tx*4]);
            float am[4] = {av.x,av.y,av.z,av.w};
            float bn[4] = {bv.x,bv.y,bv.z,bv.w};
            #pragma unroll
            for (int i=0;i<4;i++){
                #pragma unroll
                for (int j=0;j<4;j++) acc[i][j] += am[i]*bn[j];
            }
        }
        __syncthreads();
    }
    #pragma unroll
    for (int i=0;i<4;i++){
        int gm = rowBase + ty*4 + i;
        if (gm >= M) continue;
        #pragma unroll
        for (int j=0;j<4;j++){
            int gn = colBase + tx*4 + j;
            if (gn >= N) continue;
            float v = acc[i][j];
            if (bias) v += bias[gn];
            if (act == 1) v = fmaxf(v, 0.f);
            if (Res) v += Res[(long long)gm*N + gn];
            Cb[(long long)gm*N + gn] = v;
        }
    }
}

/* ------------------------- elementwise / fused --------------------------- */
__global__ void build_hcat_k(const float* __restrict__ x, const float* __restrict__ W_in,
                             const float* __restrict__ b_in, const float* __restrict__ adp,
                             float* __restrict__ out)
{
    long long idx = (long long)blockIdx.x*blockDim.x + threadIdx.x;
    if (idx >= (long long)MM*DD) return;
    int d = (int)(idx % DD);
    long long tn = idx / DD;          /* t*NN + n (t-major) */
    int n = (int)(tn % NN);
    int t = (int)(tn / NN);
    float v;
    if (d < 24){
        const float* xr = x + ((long long)n*TT + t)*3;
        v = b_in[d] + xr[0]*W_in[d] + xr[1]*W_in[24+d] + xr[2]*W_in[48+d];
    } else {
        v = adp[tn*80 + (d-24)];
    }
    out[idx] = v;
}

__global__ void softmax_k(float* __restrict__ g)
{
    long long row = (long long)blockIdx.x*4 + (threadIdx.x>>5);
    if (row >= MM) return;
    int lane = threadIdx.x & 31;
    float* p = g + row*NN;
    float r[13];
    float mx = -3.4e38f;
    #pragma unroll
    for (int i=0;i<13;i++){ int j=lane+i*32; r[i] = (j<NN)? p[j] : -3.4e38f; mx = fmaxf(mx, r[i]); }
    #pragma unroll
    for (int o=16;o;o>>=1) mx = fmaxf(mx, __shfl_xor_sync(0xffffffffu, mx, o));
    float s = 0.f;
    #pragma unroll
    for (int i=0;i<13;i++){ int j=lane+i*32; if (j<NN){ r[i]=expf(r[i]-mx); s+=r[i]; } }
    #pragma unroll
    for (int o=16;o;o>>=1) s += __shfl_xor_sync(0xffffffffu, s, o);
    float inv = 1.f/s;
    #pragma unroll
    for (int i=0;i<13;i++){ int j=lane+i*32; if (j<NN) p[j] = r[i]*inv; }
}

/* kvs[b,h,m,d] = sum_l kn[l,m]*v[l,d] ; ksum[b,h,m] = sum_l kn[l,m] */
__global__ void attn_kvs_k(const float* __restrict__ qkv, float* __restrict__ kvs,
                           float* __restrict__ ksum, int L, int spatial)
{
    int b = blockIdx.x, h = blockIdx.y;
    __shared__ float sk[32][27];
    __shared__ float sv[32][27];
    __shared__ float ss[32];
    int tid = threadIdx.x;
    int mi[3], di[3]; bool ok[3];
    #pragma unroll
    for (int i=0;i<3;i++){ int p=tid+i*256; ok[i]=(p<676); mi[i]=p/26; di[i]=p-26*(p/26); }
    float acc[3] = {0.f,0.f,0.f};
    float asum = 0.f;
    for (int l0=0; l0<L; l0+=32){
        int lc = min(32, L-l0);
        for (int idx=tid; idx<lc*26; idx+=256){
            int r = idx/26, c = idx-r*26;
            int l = l0 + r;
            long long base = spatial ? ((long long)b*NN + l)*QKVW : ((long long)l*NN + b)*QKVW;
            sk[r][c] = qkv[base + DD   + h*HD + c];
            sv[r][c] = qkv[base + 2*DD + h*HD + c];
        }
        __syncthreads();
        if (tid < lc){
            float s=0.f;
            #pragma unroll
            for (int c=0;c<26;c++){ float k=sk[tid][c]; s += k*k; }
            ss[tid] = 1.f/fmaxf(sqrtf(s), 1e-12f);
        }
        __syncthreads();
        for (int idx=tid; idx<lc*26; idx+=256){
            int r = idx/26, c = idx-r*26;
            sk[r][c] *= ss[r];
        }
        __syncthreads();
        for (int l=0;l<lc;l++){
            #pragma unroll
            for (int i=0;i<3;i++)
                if (ok[i]) acc[i] += sk[l][mi[i]]*sv[l][di[i]];
        }
        if (tid < 26){
            for (int l=0;l<lc;l++) asum += sk[l][tid];
        }
        __syncthreads();
    }
    long long ob = ((long long)b*HH + h);
    #pragma unroll
    for (int i=0;i<3;i++){ int p=tid+i*256; if (p<676) kvs[ob*676 + p] = acc[i]; }
    if (tid<26) ksum[ob*26 + tid] = asum;
}

/* out = (qn@kvs + L*v) / (qn.ksum + L) ; one warp per (b,h,l) */
__global__ void attn_out_k(const float* __restrict__ qkv, const float* __restrict__ kvs,
                           const float* __restrict__ ksum, float* __restrict__ cat,
                           int L, int spatial)
{
    int b = blockIdx.x, h = blockIdx.y;
    int warp = threadIdx.x >> 5, lane = threadIdx.x & 31;
    __shared__ float skv[676];
    __shared__ float sks[26];
    long long ob = ((long long)b*HH + h);
    for (int idx=threadIdx.x; idx<676; idx+=128) skv[idx] = kvs[ob*676+idx];
    if (threadIdx.x < 26) sks[threadIdx.x] = ksum[ob*26+threadIdx.x];
    __syncthreads();
    int l = blockIdx.z*4 + warp;
    if (l >= L) return;
    long long base = spatial ? ((long long)b*NN + l)*QKVW : ((long long)l*NN + b)*QKVW;
    float q = (lane < 26) ? qkv[base + h*HD + lane] : 0.f;
    float sq = q*q;
    #pragma unroll
    for (int o=16;o;o>>=1) sq += __shfl_xor_sync(0xffffffffu, sq, o);
    float qn = q * (1.f/fmaxf(sqrtf(sq), 1e-12f));
    float dp = (lane<26) ? qn*sks[lane] : 0.f;
    #pragma unroll
    for (int o=16;o;o>>=1) dp += __shfl_xor_sync(0xffffffffu, dp, o);
    float den = dp + (float)L;
    float num = 0.f;
    #pragma unroll
    for (int m=0;m<26;m++){
        float qm = __shfl_sync(0xffffffffu, qn, m);
        if (lane < 26) num += qm * skv[m*26 + lane];
    }
    if (lane < 26){
        float v = qkv[base + 2*DD + h*HD + lane];
        float o = (num + (float)L * v)/den;
        long long cb = spatial ? ((long long)b*NN + l)*CATW + h*HD
                               : ((long long)l*NN + b)*CATW + DD + h*HD;
        cat[cb + lane] = o;
    }
}

/* h1 = LN(2*(h + a0*pw0 + 0.01*a1*pw1)) */
__global__ void combine_ln1_k(const float* __restrict__ h, const float* __restrict__ a0,
                              const float* __restrict__ pw0, const float* __restrict__ a1,
                              const float* __restrict__ pw1, const float* __restrict__ gam,
                              const float* __restrict__ bet, float* __restrict__ out)
{
    long long row = (long long)blockIdx.x*4 + (threadIdx.x>>5);
    if (row >= MM) return;
    int lane = threadIdx.x & 31;
    long long base = row*DD;
    float v[4]; float s = 0.f;
    #pragma unroll
    for (int i=0;i<4;i++){
        int j = lane + i*32;
        if (j < DD){
            float x = 2.f*(h[base+j] + a0[base+j]*pw0[base+j] + 0.01f*a1[base+j]*pw1[base+j]);
            v[i]=x; s+=x;
        } else v[i]=0.f;
    }
    #pragma unroll
    for (int o=16;o;o>>=1) s += __shfl_xor_sync(0xffffffffu, s, o);
    float mean = s * (1.f/DD);
    float vs = 0.f;
    #pragma unroll
    for (int i=0;i<4;i++){ int j=lane+i*32; if (j<DD){ float d=v[i]-mean; vs += d*d; } }
    #pragma unroll
    for (int o=16;o;o>>=1) vs += __shfl_xor_sync(0xffffffffu, vs, o);
    float inv = rsqrtf(vs*(1.f/DD) + 1e-5f);
    #pragma unroll
    for (int i=0;i<4;i++){ int j=lane+i*32; if (j<DD) out[base+j] = (v[i]-mean)*inv*gam[j] + bet[j]; }
}

__global__ void ln_k(const float* __restrict__ in, const float* __restrict__ gam,
                     const float* __restrict__ bet, float* __restrict__ out)
{
    long long row = (long long)blockIdx.x*4 + (threadIdx.x>>5);
    if (row >= MM) return;
    int lane = threadIdx.x & 31;
    const float* p = in + row*DD;
    float v[4]; float s = 0.f;
    #pragma unroll
    for (int i=0;i<4;i++){ int j=lane+i*32; v[i] = (j<DD)? p[j] : 0.f; s += v[i]; }
    #pragma unroll
    for (int o=16;o;o>>=1) s += __shfl_xor_sync(0xffffffffu, s, o);
    float mean = s * (1.f/DD);
    float vs = 0.f;
    #pragma unroll
    for (int i=0;i<4;i++){ int j=lane+i*32; if (j<DD){ float d=v[i]-mean; vs += d*d; } }
    #pragma unroll
    for (int o=16;o;o>>=1) vs += __shfl_xor_sync(0xffffffffu, vs, o);
    float inv = rsqrtf(vs*(1.f/DD) + 1e-5f);
    float* q = out + row*DD;
    #pragma unroll
    for (int i=0;i<4;i++){ int j=lane+i*32; if (j<DD) q[j] = (v[i]-mean)*inv*gam[j] + bet[j]; }
}

/* h2 [T,N,D] -> h2T [N, T*D] */
__global__ void transpose_k(const float* __restrict__ in, float* __restrict__ out)
{
    long long idx = (long long)blockIdx.x*blockDim.x + threadIdx.x;
    if (idx >= (long long)MM*DD) return;
    int d = (int)(idx % DD);
    long long tn = idx / DD;
    int n = (int)(tn % NN);
    int t = (int)(tn / NN);
    out[(long long)n*(TT*DD) + (long long)t*DD + d] = in[idx];
}

__global__ void ep_reduce_k(const float* __restrict__ part, const float* __restrict__ ep_b,
                            float* __restrict__ y)
{
    int idx = blockIdx.x*blockDim.x + threadIdx.x;
    if (idx >= NN*DD) return;
    float s = ep_b[idx % DD];
    #pragma unroll
    for (int j=0;j<EPK_SPLIT;j++) s += part[(long long)j*(NN*DD) + idx];
    y[idx] = s;
}

/* ------------------------------ host side -------------------------------- */
static void gemm(const float*A,const float*B,const float*bias,const float*Res,float*C,
                 int M,int N,int K,long long sA,long long sB,long long sC,
                 int transB,int act,int kChunk,int batch)
{
    dim3 grid((N+63)/64, (M+63)/64, batch);
    gemm_k<<<grid, 256>>>(A,B,bias,Res,C,M,N,K,sA,sB,sC,transB,act,kChunk);
}

static void gemm_tf(const float*A,const float*B,const float*bias,const float*Res,float*C,
                    int M,int N,int K,long long sA,long long sB,long long sC,
                    int transB,int act,int kChunk,int batch)
{
    dim3 grid((N+63)/64, (M+255)/256, batch);
    if (transB) gemm_f16_k<1><<<grid, 256>>>(A,B,bias,Res,C,M,N,K,sA,sB,sC,act,kChunk);
    else        gemm_f16_k<0><<<grid, 256>>>(A,B,bias,Res,C,M,N,K,sA,sB,sC,act,kChunk);
}

extern "C" void kernel_launch(void* const* d_in, const int* in_sizes, int n_in,
                              void* d_out, int out_size)
{
    const float* x     = (const float*)d_in[0];
    const float* W_in  = (const float*)d_in[1];
    const float* b_in  = (const float*)d_in[2];
    const float* adp   = (const float*)d_in[3];
    const float* W_tp  = (const float*)d_in[4];
    const float* b_tp  = (const float*)d_in[5];
    const float* qkv_w = (const float*)d_in[6];
    const float* op_w  = (const float*)d_in[7];
    const float* op_b  = (const float*)d_in[8];
    const float* pw_w  = (const float*)d_in[9];
    const float* pw_b  = (const float*)d_in[10];
    const float* fc_w1 = (const float*)d_in[11];
    const float* fc_b1 = (const float*)d_in[12];
    const float* fc_w2 = (const float*)d_in[13];
    const float* fc_b2 = (const float*)d_in[14];
    const float* ln1_g = (const float*)d_in[15];
    const float* ln1_b = (const float*)d_in[16];
    const float* ln2_g = (const float*)d_in[17];
    const float* ln2_b = (const float*)d_in[18];
    const float* ep_w  = (const float*)d_in[19];
    const float* ep_b  = (const float*)d_in[20];
    const float* enc_w1= (const float*)d_in[21];
    const float* enc_b1= (const float*)d_in[22];
    const float* enc_w2= (const float*)d_in[23];
    const float* enc_b2= (const float*)d_in[24];
    const float* out_w = (const float*)d_in[25];
    const float* out_b = (const float*)d_in[26];
    float* out = (float*)d_out;

    float *hcat,*h,*graph,*z1,*qkv,*kvs,*ksum,*cat,*att0,*att1,*pw0,*pw1,*h1,*mid,*tmp,*h2,*h2T,*part,*y,*ymid;
    cudaGetSymbolAddress((void**)&hcat, g_hcat);
    cudaGetSymbolAddress((void**)&h,    g_h);
    cudaGetSymbolAddress((void**)&graph,g_graph);
    cudaGetSymbolAddress((void**)&z1,   g_z1);
    cudaGetSymbolAddress((void**)&qkv,  g_qkv);
    cudaGetSymbolAddress((void**)&kvs,  g_kvs);
    cudaGetSymbolAddress((void**)&ksum, g_ksum);
    cudaGetSymbolAddress((void**)&cat,  g_cat);
    cudaGetSymbolAddress((void**)&att0, g_att0);
    cudaGetSymbolAddress((void**)&att1, g_att1);
    cudaGetSymbolAddress((void**)&pw0,  g_pw0);
    cudaGetSymbolAddress((void**)&pw1,  g_pw1);
    cudaGetSymbolAddress((void**)&h1,   g_h1);
    cudaGetSymbolAddress((void**)&mid,  g_mid);
    cudaGetSymbolAddress((void**)&tmp,  g_tmp);
    cudaGetSymbolAddress((void**)&h2,   g_h2);
    cudaGetSymbolAddress((void**)&h2T,  g_h2T);
    cudaGetSymbolAddress((void**)&part, g_part);
    cudaGetSymbolAddress((void**)&y,    g_y);
    cudaGetSymbolAddress((void**)&ymid, g_ymid);

    const long long tot = (long long)MM*DD;

    /* 1. hcat = [x@W_in + b_in, adp]  -> [T,N,104] */
    build_hcat_k<<<(unsigned)((tot+255)/256), 256>>>(x, W_in, b_in, adp, hcat);

    /* 2. h = hcat @ W_tp + b_tp */
    gemm_tf(hcat, W_tp, b_tp, nullptr, h, MM, DD, DD, 0,0,0, 0,0,0, 1);

    /* 3. graph = relu(adp_t @ adp_t^T), batched over t */
    gemm_tf(adp, adp, nullptr, nullptr, graph, NN, NN, 80,
            (long long)NN*80, (long long)NN*80, (long long)NN*NN, 1, 1, 0, TT);

    /* 4. softmax rows */
    softmax_k<<<(MM+3)/4, 128>>>(graph);

    /* 5. z1 = graph @ h_t, batched over t */
    gemm_tf(graph, h, nullptr, nullptr, z1, NN, DD, NN,
            (long long)NN*NN, (long long)NN*DD, (long long)NN*DD, 0, 0, 0, TT);

    /* 6. att0 = fast_attn(h, weights[0]) */
    gemm_tf(h, qkv_w, nullptr, nullptr, qkv, MM, QKVW, DD, 0,0,0, 0,0,0, 1);
    attn_kvs_k<<<dim3(TT,HH), 256>>>(qkv, kvs, ksum, NN, 1);
    attn_out_k<<<dim3(TT,HH,(NN+3)/4), 128>>>(qkv, kvs, ksum, cat, NN, 1);
    attn_kvs_k<<<dim3(NN,HH), 256>>>(qkv, kvs, ksum, TT, 0);
    attn_out_k<<<dim3(NN,HH,(TT+3)/4), 128>>>(qkv, kvs, ksum, cat, TT, 0);
    gemm_tf(cat, op_w, op_b, nullptr, att0, MM, DD, CATW, 0,0,0, 0,0,0, 1);

    /* 7. att1 = fast_attn(z1, weights[1]) */
    gemm_tf(z1, qkv_w + DD*QKVW, nullptr, nullptr, qkv, MM, QKVW, DD, 0,0,0, 0,0,0, 1);
    attn_kvs_k<<<dim3(TT,HH), 256>>>(qkv, kvs, ksum, NN, 1);
    attn_out_k<<<dim3(TT,HH,(NN+3)/4), 128>>>(qkv, kvs, ksum, cat, NN, 1);
    attn_kvs_k<<<dim3(NN,HH), 256>>>(qkv, kvs, ksum, TT, 0);
    attn_out_k<<<dim3(NN,HH,(TT+3)/4), 128>>>(qkv, kvs, ksum, cat, TT, 0);
    gemm_tf(cat, op_w + CATW*DD, op_b + DD, nullptr, att1, MM, DD, CATW, 0,0,0, 0,0,0, 1);

    /* 8. pw projections */
    gemm_tf(h,    pw_w,         pw_b,      nullptr, pw0, MM, DD, DD, 0,0,0, 0,0,0, 1);
    gemm_tf(att0, pw_w + DD*DD, pw_b + DD, nullptr, pw1, MM, DD, DD, 0,0,0, 0,0,0, 1);

    /* 9. h1 = LN(2*(h + att0*pw0 + 0.01*att1*pw1)) */
    combine_ln1_k<<<(MM+3)/4, 128>>>(h, att0, pw0, att1, pw1, ln1_g, ln1_b, h1);

    /* 10. h2 = LN(h1 + MLP(h1)) */
    gemm_tf(h1,  fc_w1, fc_b1, nullptr, mid, MM, CATW, DD,  0,0,0, 0,1,0, 1);
    gemm_tf(mid, fc_w2, fc_b2, h1,      tmp, MM, DD, CATW,  0,0,0, 0,0,0, 1);
    ln_k<<<(MM+3)/4, 128>>>(tmp, ln2_g, ln2_b, h2);

    /* 11. encoder_proj: y = reshape(h2) @ ep_w + ep_b  (split-K, deterministic) */
    transpose_k<<<(unsigned)((tot+255)/256), 256>>>(h2, h2T);
    gemm_tf(h2T, ep_w, nullptr, nullptr, part, NN, DD, TT*DD,
            0, 0, (long long)NN*DD, 0, 0, EPK_CHUNK, EPK_SPLIT);
    ep_reduce_k<<<(NN*DD+255)/256, 256>>>(part, ep_b, y);

    /* 12. three residual MLP blocks (small; fp32) */
    for (int i=0;i<3;i++){
        gemm(y,    enc_w1 + (long long)i*DD*CATW, enc_b1 + i*CATW, nullptr, ymid, NN, CATW, DD, 0,0,0, 0,1,0, 1);
        gemm(ymid, enc_w2 + (long long)i*CATW*DD, enc_b2 + i*DD,   y,       y,    NN, DD, CATW, 0,0,0, 0,0,0, 1);
    }

    /* 13. out = y @ out_w + out_b -> [N,365] == d_out layout */
    gemm(y, out_w, out_b, nullptr, out, NN, TT, DD, 0,0,0, 0,0,0, 1);
}